// round 10
// baseline (speedup 1.0000x reference)
#include <cuda_runtime.h>
#include <cuda_bf16.h>
#include <cstdint>
#include <math.h>

// ===========================================================================
#define T_TOK   65536
#define NWIN    4096
#define NPIX    4096

// scratch (device globals)
__device__ float g_X  [T_TOK * 128];
__device__ float g_QKV[T_TOK * 384];
__device__ float g_Hid[(size_t)T_TOK * 512];   // NHWC x / mlp hidden / attn S
__device__ float g_Xr [T_TOK * 128];
__device__ float g_Vt [512 * 64 * 256];
__device__ float g_h  [NPIX * 128];
__device__ float g_c0b[NPIX * 128];
__device__ float g_c1b[NPIX * 128];
__device__ float g_gates0[NPIX * 512];
__device__ float g_gates1[NPIX * 512];
__device__ float g_Wc [128 * 512];
__device__ float g_Wl [512 * 256];

__device__ __forceinline__ uint32_t f2tf32(float f) {
    uint32_t u; asm("cvt.rna.tf32.f32 %0, %1;" : "=r"(u) : "f"(f)); return u;
}
__device__ __forceinline__ void mma_tf32(float* c, const uint32_t* a, const uint32_t* b) {
    asm volatile(
        "mma.sync.aligned.m16n8k8.row.col.f32.tf32.tf32.f32 "
        "{%0,%1,%2,%3}, {%4,%5,%6,%7}, {%8,%9}, {%0,%1,%2,%3};"
        : "+f"(c[0]), "+f"(c[1]), "+f"(c[2]), "+f"(c[3])
        : "r"(a[0]), "r"(a[1]), "r"(a[2]), "r"(a[3]), "r"(b[0]), "r"(b[1]));
}

// ===========================================================================
// prep kernels
// ===========================================================================
__global__ void prep_convw(const float* __restrict__ cw, float* __restrict__ Wc) {
    int idx = blockIdx.x * 128 + threadIdx.x;
    int o = idx >> 9, rem = idx & 511, tap = rem >> 7, i = rem & 127;
    Wc[idx] = cw[o * 512 + i * 4 + tap];
}
__global__ void prep_lstmw(const float* __restrict__ wx, const float* __restrict__ wh,
                           float* __restrict__ Wl) {
    int idx = blockIdx.x * 128 + threadIdx.x;
    int o = idx >> 8, k = idx & 255;
    Wl[idx] = (k < 128) ? wx[o * 128 + k] : wh[o * 128 + (k - 128)];
}
__global__ void init_hc(const float* __restrict__ h0, const float* __restrict__ c0,
                        float* __restrict__ h, float* __restrict__ c) {
    int idx = blockIdx.x * 128 + threadIdx.x;
    int ch = idx >> 12, p = idx & 4095;
    h[p * 128 + ch] = h0[idx];
    c[p * 128 + ch] = c0[idx];
}

// NCHW -> NHWC transpose of x (output 33.5M floats -> g_Hid)
__global__ void transpose_x(const float* __restrict__ x, float* __restrict__ xt) {
    __shared__ float t[32][33];
    int bid = blockIdx.x;
    int tile = bid & 15, by = bid >> 4;
    int i0 = (tile >> 2) * 32, x0 = (tile & 3) * 32;
    int tx = threadIdx.x & 31, ty = threadIdx.x >> 5;
    const float* xin = x + (size_t)(by >> 7) * 2097152 + (size_t)(by & 127) * 128;
#pragma unroll
    for (int k = 0; k < 4; k++)
        t[ty + k * 8][tx] = xin[(size_t)(i0 + ty + k * 8) * 16384 + x0 + tx];
    __syncthreads();
    float* xout = xt + (size_t)by * 16384;
#pragma unroll
    for (int k = 0; k < 4; k++)
        xout[(size_t)(x0 + ty + k * 8) * 128 + i0 + tx] = t[tx][ty + k * 8];
}

// ===========================================================================
// generic mma.sync tf32 GEMM, double-buffered (R8 version).
// MODE: 0 plain | 1 conv-im2col A | 3 attn QK^T | 4 attn PV
// EPI: 0 bias | 1 bias+gelu | 2 bias+add-in-place | 3 scale | 4 add-in-place
//      6 bias + add-R + scatter window-reverse
// ===========================================================================
template<int MODE>
__device__ __forceinline__ const float* a_ptr(const float* A, int lda,
                                              int m, int k0, int blh) {
    if constexpr (MODE == 1) {
        int w = m >> 4, pl = m & 15;
        int b = w >> 8, yg = (w >> 4) & 15, xg = w & 15;
        int yl = pl >> 2, xl = pl & 3;
        int tap = k0 >> 7, ky = tap >> 1, kx = tap & 1;
        int Y = yg * 8 + yl * 2 + ky, XX = xg * 8 + xl * 2 + kx;
        return A + ((size_t)(b * 128 + Y) * 128 + XX) * 128 + (k0 & 127);
    } else if constexpr (MODE == 3) {
        int b = blh >> 5, l = (blh >> 1) & 15, h = blh & 1;
        return A + ((size_t)((b * 256 + m) * 16 + l)) * 384 + h * 64 + k0;
    } else if constexpr (MODE == 4) {
        return A + (size_t)blh * 65536 + (size_t)m * 256 + k0;
    } else {
        return A + (size_t)m * lda + k0;
    }
}
template<int MODE>
__device__ __forceinline__ const float* b_ptr(const float* B, int ldb, int n, int k0, int blh) {
    if constexpr (MODE == 3) {
        int b = blh >> 5, l = (blh >> 1) & 15, h = blh & 1;
        return B + ((size_t)((b * 256 + n) * 16 + l)) * 384 + 128 + h * 64 + k0;
    } else if constexpr (MODE == 4) {
        return B + (size_t)blh * 16384 + (size_t)n * 256 + k0;
    } else {
        return B + (size_t)n * ldb + k0;
    }
}

__device__ __forceinline__ float gelu_exact(float v) {
    return 0.5f * v * (1.0f + erff(v * 0.70710678118654752f));
}

template<int MODE, int EPI, int NT>
__global__ void __launch_bounds__(256) mma_gemm(
        const float* __restrict__ A, int lda,
        const float* __restrict__ B, int ldb,
        const float* __restrict__ bias, const float* __restrict__ R,
        float* __restrict__ C, int ldc, int K) {
    constexpr int MW = (NT == 128) ? 2 : 4;
    constexpr int NW = 8 / MW;
    constexpr int WM = 128 / MW;
    constexpr int WN = NT / NW;
    constexpr int MI = WM / 16;
    constexpr int NI = WN / 8;
    constexpr int BUF = (128 + NT) * 36;

    extern __shared__ __align__(16) uint32_t sm[];
    __shared__ float sbias[NT];

    const int tid = threadIdx.x, wid = tid >> 5, lane = tid & 31;
    const int bm = blockIdx.y * 128, bn = blockIdx.x * NT;
    const int blh = blockIdx.z;
    const int wm0 = (wid & (MW - 1)) * WM;
    const int wn0 = (wid / MW) * WN;
    const int srow = tid >> 3, scol = tid & 7;

    if (EPI == 0 || EPI == 1 || EPI == 2 || EPI == 6) {
        for (int i = tid; i < NT; i += 256) sbias[i] = bias[bn + i];
    }

    float acc[MI][NI][4];
#pragma unroll
    for (int mi = 0; mi < MI; mi++)
#pragma unroll
        for (int ni = 0; ni < NI; ni++)
#pragma unroll
            for (int q = 0; q < 4; q++) acc[mi][ni][q] = 0.f;

    float4 aReg[4];
    float4 bReg[NT / 32];

    auto ldg = [&](int k0) {
#pragma unroll
        for (int it = 0; it < 4; it++)
            aReg[it] = ((const float4*)a_ptr<MODE>(A, lda, bm + it * 32 + srow, k0, blh))[scol];
#pragma unroll
        for (int it = 0; it < NT / 32; it++)
            bReg[it] = ((const float4*)b_ptr<MODE>(B, ldb, bn + it * 32 + srow, k0, blh))[scol];
    };
    auto sts = [&](int buf) {
        uint32_t* base = sm + buf * BUF;
#pragma unroll
        for (int it = 0; it < 4; it++) {
            float4 v = aReg[it];
            uint4 u = make_uint4(f2tf32(v.x), f2tf32(v.y), f2tf32(v.z), f2tf32(v.w));
            *(uint4*)&base[(it * 32 + srow) * 36 + scol * 4] = u;
        }
        uint32_t* bb = base + 128 * 36;
#pragma unroll
        for (int it = 0; it < NT / 32; it++) {
            float4 v = bReg[it];
            uint4 u = make_uint4(f2tf32(v.x), f2tf32(v.y), f2tf32(v.z), f2tf32(v.w));
            *(uint4*)&bb[(it * 32 + srow) * 36 + scol * 4] = u;
        }
    };
    auto compute = [&](int buf) {
        const uint32_t* Ab = sm + buf * BUF;
        const uint32_t* Bb = Ab + 128 * 36;
#pragma unroll
        for (int ks = 0; ks < 4; ks++) {
            int kq = ks * 8 + (lane & 3);
            uint32_t afr[MI][4];
#pragma unroll
            for (int mi = 0; mi < MI; mi++) {
                int r = wm0 + mi * 16 + (lane >> 2);
                afr[mi][0] = Ab[r * 36 + kq];
                afr[mi][1] = Ab[(r + 8) * 36 + kq];
                afr[mi][2] = Ab[r * 36 + kq + 4];
                afr[mi][3] = Ab[(r + 8) * 36 + kq + 4];
            }
            uint32_t bfr[NI][2];
#pragma unroll
            for (int ni = 0; ni < NI; ni++) {
                int n = wn0 + ni * 8 + (lane >> 2);
                bfr[ni][0] = Bb[n * 36 + kq];
                bfr[ni][1] = Bb[n * 36 + kq + 4];
            }
#pragma unroll
            for (int mi = 0; mi < MI; mi++)
#pragma unroll
                for (int ni = 0; ni < NI; ni++)
                    mma_tf32(acc[mi][ni], afr[mi], bfr[ni]);
        }
    };

    const int NCH = K >> 5;
    ldg(0);
    sts(0);
    int cur = 0;
    for (int ch = 0; ch < NCH; ch++) {
        __syncthreads();
        if (ch + 1 < NCH) ldg((ch + 1) << 5);
        compute(cur);
        if (ch + 1 < NCH) sts(cur ^ 1);
        cur ^= 1;
    }

    // ---- epilogue ----
#pragma unroll
    for (int mi = 0; mi < MI; mi++) {
#pragma unroll
        for (int ni = 0; ni < NI; ni++) {
#pragma unroll
            for (int half = 0; half < 2; half++) {
                int row = bm + wm0 + mi * 16 + (lane >> 2) + half * 8;
                int cl = wn0 + ni * 8 + 2 * (lane & 3);
                float f0 = acc[mi][ni][half * 2 + 0];
                float f1 = acc[mi][ni][half * 2 + 1];
                if constexpr (EPI == 0 || EPI == 2 || EPI == 6) { f0 += sbias[cl]; f1 += sbias[cl + 1]; }
                else if constexpr (EPI == 1) { f0 = gelu_exact(f0 + sbias[cl]); f1 = gelu_exact(f1 + sbias[cl + 1]); }
                else if constexpr (EPI == 3) { f0 *= 0.08838834764831843f; f1 *= 0.08838834764831843f; }
                float* cp;
                if constexpr (MODE == 4) {
                    int b = blh >> 5, l = (blh >> 1) & 15, h = blh & 1;
                    cp = C + ((size_t)((b * 256 + row) * 16 + l)) * 128 + h * 64 + cl;
                } else if constexpr (MODE == 3) {
                    cp = C + (size_t)blh * 65536 + (size_t)row * 256 + bn + cl;
                } else if constexpr (EPI == 6) {
                    int n_ = row >> 12, w_ = (row >> 4) & 255, pl = row & 15;
                    int p = ((w_ >> 4) * 4 + (pl >> 2)) * 64 + (w_ & 15) * 4 + (pl & 3);
                    cp = C + ((size_t)n_ * 4096 + p) * 128 + bn + cl;
                } else {
                    cp = C + (size_t)row * ldc + bn + cl;
                }
                float2 v = make_float2(f0, f1);
                if constexpr (EPI == 2 || EPI == 4) {
                    float2 o = *(float2*)cp;
                    v.x += o.x; v.y += o.y;
                }
                if constexpr (EPI == 6) {
                    float2 o = *(const float2*)(R + (size_t)row * ldc + bn + cl);
                    v.x += o.x; v.y += o.y;
                }
                *(float2*)cp = v;
            }
        }
    }
}

// ===========================================================================
// attention 1: per window (16 tokens, 2 heads, hd=64). X += attn(V)
// ===========================================================================
__global__ void attn1_kernel(const float* __restrict__ QKV, float* __restrict__ X) {
    __shared__ float q[16][384];
    __shared__ float s[2][16][16];
    int w = blockIdx.x, tid = threadIdx.x;
    size_t base = (size_t)w * 16 * 384;
    for (int i = tid; i < 16 * 384; i += 128) q[i / 384][i % 384] = QKV[base + i];
    __syncthreads();
    for (int idx = tid; idx < 512; idx += 128) {
        int h = idx >> 8, t1 = (idx >> 4) & 15, t2 = idx & 15;
        const float* qp = &q[t1][h * 64];
        const float* kp = &q[t2][128 + h * 64];
        float a = 0.f;
#pragma unroll
        for (int c = 0; c < 64; c++) a = fmaf(qp[c], kp[c], a);
        s[h][t1][t2] = a * 0.08838834764831843f;
    }
    __syncthreads();
    if (tid < 32) {
        int h = tid >> 4, t1 = tid & 15;
        float m = -1e30f;
#pragma unroll
        for (int j = 0; j < 16; j++) m = fmaxf(m, s[h][t1][j]);
        float sum = 0.f;
#pragma unroll
        for (int j = 0; j < 16; j++) { float e = expf(s[h][t1][j] - m); s[h][t1][j] = e; sum += e; }
        float inv = 1.f / sum;
#pragma unroll
        for (int j = 0; j < 16; j++) s[h][t1][j] *= inv;
    }
    __syncthreads();
    for (int idx = tid; idx < 2048; idx += 128) {
        int t1 = idx >> 7, ch = idx & 127, h = ch >> 6;
        float a = 0.f;
#pragma unroll
        for (int j = 0; j < 16; j++) a = fmaf(s[h][t1][j], q[j][256 + ch], a);
        X[(size_t)(w * 16 + t1) * 128 + ch] += a;
    }
}

// ===========================================================================
// attn2 helpers (R8 path)
// ===========================================================================
__global__ void vt_kernel(const float* __restrict__ QKV, float* __restrict__ Vt) {
    __shared__ float t[32][65];
    int blh = blockIdx.x, g0 = blockIdx.y * 32;
    int b = blh >> 5, l = (blh >> 1) & 15, h = blh & 1;
    int tid = threadIdx.x;
#pragma unroll
    for (int it = 0; it < 8; it++) {
        int e = tid + it * 256;
        int g = e >> 6, c = e & 63;
        t[g][c] = QKV[((size_t)((b * 256 + g0 + g) * 16 + l)) * 384 + 256 + h * 64 + c];
    }
    __syncthreads();
    float* vp = Vt + (size_t)blh * 16384;
#pragma unroll
    for (int it = 0; it < 8; it++) {
        int e = tid + it * 256;
        int c = e >> 5, g = e & 31;
        vp[(size_t)c * 256 + g0 + g] = t[g][c];
    }
}

__global__ void softmax_s(float* __restrict__ S) {
    int row = blockIdx.x * 8 + (threadIdx.x >> 5);
    int lane = threadIdx.x & 31;
    float* r = S + (size_t)row * 256;
    float v[8];
#pragma unroll
    for (int i = 0; i < 8; i++) v[i] = r[lane + i * 32];
    float m = -1e30f;
#pragma unroll
    for (int i = 0; i < 8; i++) m = fmaxf(m, v[i]);
#pragma unroll
    for (int o = 16; o; o >>= 1) m = fmaxf(m, __shfl_xor_sync(0xffffffffu, m, o));
    float s = 0.f;
#pragma unroll
    for (int i = 0; i < 8; i++) { v[i] = expf(v[i] - m); s += v[i]; }
#pragma unroll
    for (int o = 16; o; o >>= 1) s += __shfl_xor_sync(0xffffffffu, s, o);
    float inv = 1.f / s;
#pragma unroll
    for (int i = 0; i < 8; i++) r[lane + i * 32] = v[i] * inv;
}

// ===========================================================================
// fused LSTM step: prologue recomputes pointwise of previous step's gates
// (h into smem), then gate-GEMM for this step. 4x32 grid, 256 threads.
// Double-buffered gates/c across steps; only bn==0 writes c/out.
// ===========================================================================
template<int FIRST>
__global__ void __launch_bounds__(256) lstm_step(
        const float* __restrict__ Xn,
        const float* __restrict__ gprev, float* __restrict__ gcur,
        const float* __restrict__ cprev, float* __restrict__ ccur,
        const float* __restrict__ h0,
        const float* __restrict__ Wl, const float* __restrict__ bias,
        float* __restrict__ out, int n) {
    extern __shared__ __align__(16) float smf[];
    float* h_s = smf;                                  // [128][132]
    uint32_t* stg = (uint32_t*)(smf + 128 * 132);      // 2 x (256*36)
    __shared__ float sbias[128];

    const int tid = threadIdx.x, wid = tid >> 5, lane = tid & 31;
    const int bn = blockIdx.x, bm = blockIdx.y;
    const int P0 = bm * 128;

    if (tid < 128) sbias[tid] = bias[bn * 128 + tid];

    if (FIRST) {
        for (int i = tid; i < 128 * 128; i += 256) {
            int p = i >> 7, ch = i & 127;
            h_s[p * 132 + ch] = h0[(size_t)(P0 + p) * 128 + ch];
        }
    } else {
#pragma unroll 1
        for (int it = 0; it < 16; it++) {
            int p = wid * 16 + it;
            const float* gp = gprev + (size_t)(P0 + p) * 512;
            float fv[4], iv[4], sv[4], ov[4];
#pragma unroll
            for (int j = 0; j < 4; j++) {
                int ch = lane + j * 32;
                fv[j] = gp[ch];       iv[j] = gp[128 + ch];
                sv[j] = gp[256 + ch]; ov[j] = gp[384 + ch];
            }
            float mf = fmaxf(fmaxf(fv[0], fv[1]), fmaxf(fv[2], fv[3]));
            float mi = fmaxf(fmaxf(iv[0], iv[1]), fmaxf(iv[2], iv[3]));
            float mo = fmaxf(fmaxf(ov[0], ov[1]), fmaxf(ov[2], ov[3]));
#pragma unroll
            for (int o = 16; o; o >>= 1) {
                mf = fmaxf(mf, __shfl_xor_sync(0xffffffffu, mf, o));
                mi = fmaxf(mi, __shfl_xor_sync(0xffffffffu, mi, o));
                mo = fmaxf(mo, __shfl_xor_sync(0xffffffffu, mo, o));
            }
            float sf = 0.f, si = 0.f, so = 0.f;
#pragma unroll
            for (int j = 0; j < 4; j++) {
                fv[j] = expf(fv[j] - mf); sf += fv[j];
                iv[j] = expf(iv[j] - mi); si += iv[j];
                ov[j] = expf(ov[j] - mo); so += ov[j];
            }
#pragma unroll
            for (int o = 16; o; o >>= 1) {
                sf += __shfl_xor_sync(0xffffffffu, sf, o);
                si += __shfl_xor_sync(0xffffffffu, si, o);
                so += __shfl_xor_sync(0xffffffffu, so, o);
            }
            float rf = 1.f / sf, ri = 1.f / si, ro = 1.f / so;
#pragma unroll
            for (int j = 0; j < 4; j++) {
                int ch = lane + j * 32;
                float cc = cprev[(size_t)(P0 + p) * 128 + ch];
                float cn = fv[j] * rf * cc + iv[j] * ri * tanhf(sv[j]);
                float hn = ov[j] * ro * tanhf(cn);
                h_s[p * 132 + ch] = hn;
                if (bn == 0) ccur[(size_t)(P0 + p) * 128 + ch] = cn;
            }
        }
    }
    __syncthreads();

    if (!FIRST && bn == 0) {
        float* ob = out + ((size_t)(n - 1) * 128) * 4096 + P0;
        for (int i = tid; i < 128 * 128; i += 256) {
            int ch = i >> 7, p = i & 127;
            ob[(size_t)ch * 4096 + p] = h_s[p * 132 + ch];
        }
    }

    // ---- GEMM: gates[P0..+128][bn*128..+128] = [Xn | h_s] @ Wl^T + bias ----
    const int wm0 = (wid & 1) * 64;
    const int wn0 = (wid >> 1) * 32;
    const int srow = tid >> 3, scol = tid & 7;
    constexpr int BUF = 256 * 36;

    float acc[4][4][4];
#pragma unroll
    for (int mi = 0; mi < 4; mi++)
#pragma unroll
        for (int ni = 0; ni < 4; ni++)
#pragma unroll
            for (int q = 0; q < 4; q++) acc[mi][ni][q] = 0.f;

    float4 aReg[4], bReg[4];
    auto ldg = [&](int k0) {
        if (k0 < 128) {
#pragma unroll
            for (int it = 0; it < 4; it++)
                aReg[it] = *(const float4*)&Xn[(size_t)(P0 + it * 32 + srow) * 128 + k0 + scol * 4];
        }
#pragma unroll
        for (int it = 0; it < 4; it++)
            bReg[it] = *(const float4*)&Wl[(size_t)(bn * 128 + it * 32 + srow) * 256 + k0 + scol * 4];
    };
    auto sts = [&](int buf, int k0) {
        uint32_t* base = stg + buf * BUF;
#pragma unroll
        for (int it = 0; it < 4; it++) {
            float4 v;
            if (k0 < 128) v = aReg[it];
            else          v = *(const float4*)&h_s[(it * 32 + srow) * 132 + (k0 - 128) + scol * 4];
            uint4 u = make_uint4(f2tf32(v.x), f2tf32(v.y), f2tf32(v.z), f2tf32(v.w));
            *(uint4*)&base[(it * 32 + srow) * 36 + scol * 4] = u;
        }
        uint32_t* bb = base + 128 * 36;
#pragma unroll
        for (int it = 0; it < 4; it++) {
            float4 v = bReg[it];
            uint4 u = make_uint4(f2tf32(v.x), f2tf32(v.y), f2tf32(v.z), f2tf32(v.w));
            *(uint4*)&bb[(it * 32 + srow) * 36 + scol * 4] = u;
        }
    };
    auto compute = [&](int buf) {
        const uint32_t* Ab = stg + buf * BUF;
        const uint32_t* Bb = Ab + 128 * 36;
#pragma unroll
        for (int ks = 0; ks < 4; ks++) {
            int kq = ks * 8 + (lane & 3);
            uint32_t afr[4][4];
#pragma unroll
            for (int mi = 0; mi < 4; mi++) {
                int r = wm0 + mi * 16 + (lane >> 2);
                afr[mi][0] = Ab[r * 36 + kq];
                afr[mi][1] = Ab[(r + 8) * 36 + kq];
                afr[mi][2] = Ab[r * 36 + kq + 4];
                afr[mi][3] = Ab[(r + 8) * 36 + kq + 4];
            }
            uint32_t bfr[4][2];
#pragma unroll
            for (int ni = 0; ni < 4; ni++) {
                int nn = wn0 + ni * 8 + (lane >> 2);
                bfr[ni][0] = Bb[nn * 36 + kq];
                bfr[ni][1] = Bb[nn * 36 + kq + 4];
            }
#pragma unroll
            for (int mi = 0; mi < 4; mi++)
#pragma unroll
                for (int ni = 0; ni < 4; ni++)
                    mma_tf32(acc[mi][ni], afr[mi], bfr[ni]);
        }
    };

    ldg(0);
    sts(0, 0);
    int cur = 0;
    for (int ch = 0; ch < 8; ch++) {
        __syncthreads();
        if (ch + 1 < 8) ldg((ch + 1) << 5);
        compute(cur);
        if (ch + 1 < 8) sts(cur ^ 1, (ch + 1) << 5);
        cur ^= 1;
    }

#pragma unroll
    for (int mi = 0; mi < 4; mi++) {
#pragma unroll
        for (int ni = 0; ni < 4; ni++) {
#pragma unroll
            for (int half = 0; half < 2; half++) {
                int row = wm0 + mi * 16 + (lane >> 2) + half * 8;
                int cl = wn0 + ni * 8 + 2 * (lane & 3);
                float2 v = make_float2(acc[mi][ni][half * 2 + 0] + sbias[cl],
                                       acc[mi][ni][half * 2 + 1] + sbias[cl + 1]);
                *(float2*)&gcur[(size_t)(P0 + row) * 512 + bn * 128 + cl] = v;
            }
        }
    }
}

// ===========================================================================
// final LSTM pointwise (for gates_15 -> out[15], hf, cf)
// ===========================================================================
__device__ __forceinline__ float softmax128(float v, float* red) {
    const unsigned FULL = 0xffffffffu;
    float m = v;
#pragma unroll
    for (int o = 16; o; o >>= 1) m = fmaxf(m, __shfl_xor_sync(FULL, m, o));
    if ((threadIdx.x & 31) == 0) red[threadIdx.x >> 5] = m;
    __syncthreads();
    m = fmaxf(fmaxf(red[0], red[1]), fmaxf(red[2], red[3]));
    __syncthreads();
    float e = expf(v - m), s = e;
#pragma unroll
    for (int o = 16; o; o >>= 1) s += __shfl_xor_sync(FULL, s, o);
    if ((threadIdx.x & 31) == 0) red[threadIdx.x >> 5] = s;
    __syncthreads();
    s = red[0] + red[1] + red[2] + red[3];
    __syncthreads();
    return e / s;
}

__global__ void lstm_point(const float* __restrict__ gates, float* __restrict__ h,
                           float* __restrict__ cst, float* __restrict__ out, int n) {
    __shared__ float red[4];
    int p = blockIdx.x, tid = threadIdx.x;
    float f  = gates[p * 512 + tid];
    float ig = gates[p * 512 + 128 + tid];
    float s  = gates[p * 512 + 256 + tid];
    float o  = gates[p * 512 + 384 + tid];
    f  = softmax128(f,  red);
    ig = softmax128(ig, red);
    o  = softmax128(o,  red);
    float cc = cst[p * 128 + tid];
    float cn = f * cc + ig * tanhf(s);
    float hn = o * tanhf(cn);
    cst[p * 128 + tid] = cn;
    h[p * 128 + tid]   = hn;
    out[((size_t)(n * 128 + tid)) * 4096 + p] = hn;
    if (n == 15) {
        out[((size_t)(16 * 128 + tid)) * 4096 + p] = hn;
        out[((size_t)(17 * 128 + tid)) * 4096 + p] = cn;
    }
}

// ===========================================================================
extern "C" void kernel_launch(void* const* d_in, const int* in_sizes, int n_in,
                              void* d_out, int out_size) {
    const float* x       = (const float*)d_in[0];
    const float* h0      = (const float*)d_in[1];
    const float* c0      = (const float*)d_in[2];
    const float* conv_w  = (const float*)d_in[3];
    const float* conv_b  = (const float*)d_in[4];
    const float* qkv1_w  = (const float*)d_in[5];
    const float* qkv1_b  = (const float*)d_in[6];
    const float* mlp1_w1 = (const float*)d_in[7];
    const float* mlp1_b1 = (const float*)d_in[8];
    const float* mlp1_w2 = (const float*)d_in[9];
    const float* mlp1_b2 = (const float*)d_in[10];
    const float* qkv2_w  = (const float*)d_in[11];
    const float* qkv2_b  = (const float*)d_in[12];
    const float* mlp2_w1 = (const float*)d_in[13];
    const float* mlp2_b1 = (const float*)d_in[14];
    const float* mlp2_w2 = (const float*)d_in[15];
    const float* mlp2_b2 = (const float*)d_in[16];
    const float* lstm_wx = (const float*)d_in[17];
    const float* lstm_wh = (const float*)d_in[18];
    const float* lstm_bh = (const float*)d_in[19];
    float* out = (float*)d_out;
    (void)in_sizes; (void)n_in; (void)out_size;

    float *X, *QKV, *Hid, *Xr, *Vt, *h, *c0b, *c1b, *gates0, *gates1, *Wc, *Wl;
    cudaGetSymbolAddress((void**)&X, g_X);
    cudaGetSymbolAddress((void**)&QKV, g_QKV);
    cudaGetSymbolAddress((void**)&Hid, g_Hid);
    cudaGetSymbolAddress((void**)&Xr, g_Xr);
    cudaGetSymbolAddress((void**)&Vt, g_Vt);
    cudaGetSymbolAddress((void**)&h, g_h);
    cudaGetSymbolAddress((void**)&c0b, g_c0b);
    cudaGetSymbolAddress((void**)&c1b, g_c1b);
    cudaGetSymbolAddress((void**)&gates0, g_gates0);
    cudaGetSymbolAddress((void**)&gates1, g_gates1);
    cudaGetSymbolAddress((void**)&Wc, g_Wc);
    cudaGetSymbolAddress((void**)&Wl, g_Wl);

    const int SM128 = 2 * (128 + 128) * 36 * 4;                 // 73728
    const int SM64  = 2 * (128 + 64) * 36 * 4;                  // 55296
    const int SMLS  = 128 * 132 * 4 + 2 * 256 * 36 * 4;         // 141312
    cudaFuncSetAttribute((const void*)mma_gemm<1, 0, 128>, cudaFuncAttributeMaxDynamicSharedMemorySize, SM128);
    cudaFuncSetAttribute((const void*)mma_gemm<0, 0, 128>, cudaFuncAttributeMaxDynamicSharedMemorySize, SM128);
    cudaFuncSetAttribute((const void*)mma_gemm<0, 1, 128>, cudaFuncAttributeMaxDynamicSharedMemorySize, SM128);
    cudaFuncSetAttribute((const void*)mma_gemm<0, 2, 128>, cudaFuncAttributeMaxDynamicSharedMemorySize, SM128);
    cudaFuncSetAttribute((const void*)mma_gemm<0, 6, 128>, cudaFuncAttributeMaxDynamicSharedMemorySize, SM128);
    cudaFuncSetAttribute((const void*)mma_gemm<3, 3, 128>, cudaFuncAttributeMaxDynamicSharedMemorySize, SM128);
    cudaFuncSetAttribute((const void*)mma_gemm<4, 4, 64>,  cudaFuncAttributeMaxDynamicSharedMemorySize, SM64);
    cudaFuncSetAttribute((const void*)lstm_step<0>, cudaFuncAttributeMaxDynamicSharedMemorySize, SMLS);
    cudaFuncSetAttribute((const void*)lstm_step<1>, cudaFuncAttributeMaxDynamicSharedMemorySize, SMLS);

    prep_convw<<<512, 128>>>(conv_w, Wc);
    prep_lstmw<<<1024, 128>>>(lstm_wx, lstm_wh, Wl);
    init_hc<<<4096, 128>>>(h0, c0, h, c0b);
    transpose_x<<<32768, 256>>>(x, Hid);

    // conv as implicit-im2col GEMM
    mma_gemm<1, 0, 128><<<dim3(1, 512), 256, SM128>>>(Hid, 0, Wc, 512, conv_b, nullptr, X, 128, 512);

    // LocalMSA
    mma_gemm<0, 0, 128><<<dim3(3, 512), 256, SM128>>>(X, 128, qkv1_w, 128, qkv1_b, nullptr, QKV, 384, 128);
    attn1_kernel<<<NWIN, 128>>>(QKV, X);
    // MLP1
    mma_gemm<0, 1, 128><<<dim3(4, 512), 256, SM128>>>(X, 128, mlp1_w1, 128, mlp1_b1, nullptr, Hid, 512, 128);
    mma_gemm<0, 2, 128><<<dim3(1, 512), 256, SM128>>>(Hid, 512, mlp1_w2, 512, mlp1_b2, nullptr, X, 128, 512);

    // DilatedMSA (R8 path)
    mma_gemm<0, 0, 128><<<dim3(3, 512), 256, SM128>>>(X, 128, qkv2_w, 128, qkv2_b, nullptr, QKV, 384, 128);
    vt_kernel<<<dim3(512, 8), 256>>>(QKV, Vt);
    mma_gemm<3, 3, 128><<<dim3(2, 2, 512), 256, SM128>>>(QKV, 0, QKV, 0, nullptr, nullptr, Hid, 256, 64);
    softmax_s<<<16384, 256>>>(Hid);
    mma_gemm<4, 4, 64><<<dim3(1, 2, 512), 256, SM64>>>(Hid, 256, Vt, 256, nullptr, nullptr, X, 128, 256);
    // MLP2 (second GEMM fuses residual + window-reverse scatter into Xr)
    mma_gemm<0, 1, 128><<<dim3(4, 512), 256, SM128>>>(X, 128, mlp2_w1, 128, mlp2_b1, nullptr, Hid, 512, 128);
    mma_gemm<0, 6, 128><<<dim3(1, 512), 256, SM128>>>(Hid, 512, mlp2_w2, 512, mlp2_b2, X, Xr, 128, 512);

    // fused ConvLSTM scan: 16 gemm+pointwise steps + 1 final pointwise
    lstm_step<1><<<dim3(4, 32), 256, SMLS>>>(
        Xr, nullptr, gates0, nullptr, nullptr, h, Wl, lstm_bh, out, 0);
    for (int n = 1; n < 16; n++) {
        const float* gp = (n & 1) ? gates0 : gates1;
        float*       gc = (n & 1) ? gates1 : gates0;
        const float* cp = ((n - 1) & 1) ? c1b : c0b;
        float*       cc = (n & 1) ? c1b : c0b;
        lstm_step<0><<<dim3(4, 32), 256, SMLS>>>(
            Xr + (size_t)n * NPIX * 128, gp, gc, cp, cc, nullptr, Wl, lstm_bh, out, n);
    }
    lstm_point<<<NPIX, 128>>>(gates1, h, c1b, out, 15);
}

// round 11
// speedup vs baseline: 1.0713x; 1.0713x over previous
#include <cuda_runtime.h>
#include <cuda_bf16.h>
#include <cstdint>
#include <math.h>

// ===========================================================================
#define T_TOK   65536
#define NWIN    4096
#define NPIX    4096

// scratch (device globals)
__device__ float g_X  [T_TOK * 128];
__device__ float g_QKV[T_TOK * 384];
__device__ float g_Hid[(size_t)T_TOK * 512];   // NHWC x / mlp hidden / attn S
__device__ float g_Xr [T_TOK * 128];
__device__ float g_Vt [512 * 64 * 256];
__device__ float g_h  [NPIX * 128];
__device__ float g_c  [NPIX * 128];
__device__ float g_gates[NPIX * 512];
__device__ float g_Wc [128 * 512];
__device__ float g_Wl [512 * 256];
__device__ int   g_bar;

__device__ __forceinline__ uint32_t f2tf32(float f) {
    uint32_t u; asm("cvt.rna.tf32.f32 %0, %1;" : "=r"(u) : "f"(f)); return u;
}
__device__ __forceinline__ void mma_tf32(float* c, const uint32_t* a, const uint32_t* b) {
    asm volatile(
        "mma.sync.aligned.m16n8k8.row.col.f32.tf32.tf32.f32 "
        "{%0,%1,%2,%3}, {%4,%5,%6,%7}, {%8,%9}, {%0,%1,%2,%3};"
        : "+f"(c[0]), "+f"(c[1]), "+f"(c[2]), "+f"(c[3])
        : "r"(a[0]), "r"(a[1]), "r"(a[2]), "r"(a[3]), "r"(b[0]), "r"(b[1]));
}

// ===========================================================================
// prep kernels
// ===========================================================================
__global__ void prep_convw(const float* __restrict__ cw, float* __restrict__ Wc) {
    int idx = blockIdx.x * 128 + threadIdx.x;
    int o = idx >> 9, rem = idx & 511, tap = rem >> 7, i = rem & 127;
    Wc[idx] = cw[o * 512 + i * 4 + tap];
}
__global__ void prep_lstmw(const float* __restrict__ wx, const float* __restrict__ wh,
                           float* __restrict__ Wl) {
    int idx = blockIdx.x * 128 + threadIdx.x;
    int o = idx >> 8, k = idx & 255;
    Wl[idx] = (k < 128) ? wx[o * 128 + k] : wh[o * 128 + (k - 128)];
}
__global__ void init_hc(const float* __restrict__ h0, const float* __restrict__ c0,
                        float* __restrict__ h, float* __restrict__ c) {
    int idx = blockIdx.x * 128 + threadIdx.x;
    if (idx == 0) g_bar = 0;                    // reset persistent-kernel barrier
    int ch = idx >> 12, p = idx & 4095;
    h[p * 128 + ch] = h0[idx];
    c[p * 128 + ch] = c0[idx];
}

// NCHW -> NHWC transpose of x (output 33.5M floats -> g_Hid)
__global__ void transpose_x(const float* __restrict__ x, float* __restrict__ xt) {
    __shared__ float t[32][33];
    int bid = blockIdx.x;
    int tile = bid & 15, by = bid >> 4;
    int i0 = (tile >> 2) * 32, x0 = (tile & 3) * 32;
    int tx = threadIdx.x & 31, ty = threadIdx.x >> 5;
    const float* xin = x + (size_t)(by >> 7) * 2097152 + (size_t)(by & 127) * 128;
#pragma unroll
    for (int k = 0; k < 4; k++)
        t[ty + k * 8][tx] = xin[(size_t)(i0 + ty + k * 8) * 16384 + x0 + tx];
    __syncthreads();
    float* xout = xt + (size_t)by * 16384;
#pragma unroll
    for (int k = 0; k < 4; k++)
        xout[(size_t)(x0 + ty + k * 8) * 128 + i0 + tx] = t[tx][ty + k * 8];
}

// ===========================================================================
// generic mma.sync tf32 GEMM, double-buffered (R8 version).
// MODE: 0 plain | 1 conv-im2col A | 3 attn QK^T | 4 attn PV
// EPI: 0 bias | 1 bias+gelu | 2 bias+add-in-place | 3 scale | 4 add-in-place
//      6 bias + add-R + scatter window-reverse
// ===========================================================================
template<int MODE>
__device__ __forceinline__ const float* a_ptr(const float* A, int lda,
                                              int m, int k0, int blh) {
    if constexpr (MODE == 1) {
        int w = m >> 4, pl = m & 15;
        int b = w >> 8, yg = (w >> 4) & 15, xg = w & 15;
        int yl = pl >> 2, xl = pl & 3;
        int tap = k0 >> 7, ky = tap >> 1, kx = tap & 1;
        int Y = yg * 8 + yl * 2 + ky, XX = xg * 8 + xl * 2 + kx;
        return A + ((size_t)(b * 128 + Y) * 128 + XX) * 128 + (k0 & 127);
    } else if constexpr (MODE == 3) {
        int b = blh >> 5, l = (blh >> 1) & 15, h = blh & 1;
        return A + ((size_t)((b * 256 + m) * 16 + l)) * 384 + h * 64 + k0;
    } else if constexpr (MODE == 4) {
        return A + (size_t)blh * 65536 + (size_t)m * 256 + k0;
    } else {
        return A + (size_t)m * lda + k0;
    }
}
template<int MODE>
__device__ __forceinline__ const float* b_ptr(const float* B, int ldb, int n, int k0, int blh) {
    if constexpr (MODE == 3) {
        int b = blh >> 5, l = (blh >> 1) & 15, h = blh & 1;
        return B + ((size_t)((b * 256 + n) * 16 + l)) * 384 + 128 + h * 64 + k0;
    } else if constexpr (MODE == 4) {
        return B + (size_t)blh * 16384 + (size_t)n * 256 + k0;
    } else {
        return B + (size_t)n * ldb + k0;
    }
}

__device__ __forceinline__ float gelu_exact(float v) {
    return 0.5f * v * (1.0f + erff(v * 0.70710678118654752f));
}

template<int MODE, int EPI, int NT>
__global__ void __launch_bounds__(256) mma_gemm(
        const float* __restrict__ A, int lda,
        const float* __restrict__ B, int ldb,
        const float* __restrict__ bias, const float* __restrict__ R,
        float* __restrict__ C, int ldc, int K) {
    constexpr int MW = (NT == 128) ? 2 : 4;
    constexpr int NW = 8 / MW;
    constexpr int WM = 128 / MW;
    constexpr int WN = NT / NW;
    constexpr int MI = WM / 16;
    constexpr int NI = WN / 8;
    constexpr int BUF = (128 + NT) * 36;

    extern __shared__ __align__(16) uint32_t sm[];
    __shared__ float sbias[NT];

    const int tid = threadIdx.x, wid = tid >> 5, lane = tid & 31;
    const int bm = blockIdx.y * 128, bn = blockIdx.x * NT;
    const int blh = blockIdx.z;
    const int wm0 = (wid & (MW - 1)) * WM;
    const int wn0 = (wid / MW) * WN;
    const int srow = tid >> 3, scol = tid & 7;

    if (EPI == 0 || EPI == 1 || EPI == 2 || EPI == 6) {
        for (int i = tid; i < NT; i += 256) sbias[i] = bias[bn + i];
    }

    float acc[MI][NI][4];
#pragma unroll
    for (int mi = 0; mi < MI; mi++)
#pragma unroll
        for (int ni = 0; ni < NI; ni++)
#pragma unroll
            for (int q = 0; q < 4; q++) acc[mi][ni][q] = 0.f;

    float4 aReg[4];
    float4 bReg[NT / 32];

    auto ldg = [&](int k0) {
#pragma unroll
        for (int it = 0; it < 4; it++)
            aReg[it] = ((const float4*)a_ptr<MODE>(A, lda, bm + it * 32 + srow, k0, blh))[scol];
#pragma unroll
        for (int it = 0; it < NT / 32; it++)
            bReg[it] = ((const float4*)b_ptr<MODE>(B, ldb, bn + it * 32 + srow, k0, blh))[scol];
    };
    auto sts = [&](int buf) {
        uint32_t* base = sm + buf * BUF;
#pragma unroll
        for (int it = 0; it < 4; it++) {
            float4 v = aReg[it];
            uint4 u = make_uint4(f2tf32(v.x), f2tf32(v.y), f2tf32(v.z), f2tf32(v.w));
            *(uint4*)&base[(it * 32 + srow) * 36 + scol * 4] = u;
        }
        uint32_t* bb = base + 128 * 36;
#pragma unroll
        for (int it = 0; it < NT / 32; it++) {
            float4 v = bReg[it];
            uint4 u = make_uint4(f2tf32(v.x), f2tf32(v.y), f2tf32(v.z), f2tf32(v.w));
            *(uint4*)&bb[(it * 32 + srow) * 36 + scol * 4] = u;
        }
    };
    auto compute = [&](int buf) {
        const uint32_t* Ab = sm + buf * BUF;
        const uint32_t* Bb = Ab + 128 * 36;
#pragma unroll
        for (int ks = 0; ks < 4; ks++) {
            int kq = ks * 8 + (lane & 3);
            uint32_t afr[MI][4];
#pragma unroll
            for (int mi = 0; mi < MI; mi++) {
                int r = wm0 + mi * 16 + (lane >> 2);
                afr[mi][0] = Ab[r * 36 + kq];
                afr[mi][1] = Ab[(r + 8) * 36 + kq];
                afr[mi][2] = Ab[r * 36 + kq + 4];
                afr[mi][3] = Ab[(r + 8) * 36 + kq + 4];
            }
            uint32_t bfr[NI][2];
#pragma unroll
            for (int ni = 0; ni < NI; ni++) {
                int n = wn0 + ni * 8 + (lane >> 2);
                bfr[ni][0] = Bb[n * 36 + kq];
                bfr[ni][1] = Bb[n * 36 + kq + 4];
            }
#pragma unroll
            for (int mi = 0; mi < MI; mi++)
#pragma unroll
                for (int ni = 0; ni < NI; ni++)
                    mma_tf32(acc[mi][ni], afr[mi], bfr[ni]);
        }
    };

    const int NCH = K >> 5;
    ldg(0);
    sts(0);
    int cur = 0;
    for (int ch = 0; ch < NCH; ch++) {
        __syncthreads();
        if (ch + 1 < NCH) ldg((ch + 1) << 5);
        compute(cur);
        if (ch + 1 < NCH) sts(cur ^ 1);
        cur ^= 1;
    }

    // ---- epilogue ----
#pragma unroll
    for (int mi = 0; mi < MI; mi++) {
#pragma unroll
        for (int ni = 0; ni < NI; ni++) {
#pragma unroll
            for (int half = 0; half < 2; half++) {
                int row = bm + wm0 + mi * 16 + (lane >> 2) + half * 8;
                int cl = wn0 + ni * 8 + 2 * (lane & 3);
                float f0 = acc[mi][ni][half * 2 + 0];
                float f1 = acc[mi][ni][half * 2 + 1];
                if constexpr (EPI == 0 || EPI == 2 || EPI == 6) { f0 += sbias[cl]; f1 += sbias[cl + 1]; }
                else if constexpr (EPI == 1) { f0 = gelu_exact(f0 + sbias[cl]); f1 = gelu_exact(f1 + sbias[cl + 1]); }
                else if constexpr (EPI == 3) { f0 *= 0.08838834764831843f; f1 *= 0.08838834764831843f; }
                float* cp;
                if constexpr (MODE == 4) {
                    int b = blh >> 5, l = (blh >> 1) & 15, h = blh & 1;
                    cp = C + ((size_t)((b * 256 + row) * 16 + l)) * 128 + h * 64 + cl;
                } else if constexpr (MODE == 3) {
                    cp = C + (size_t)blh * 65536 + (size_t)row * 256 + bn + cl;
                } else if constexpr (EPI == 6) {
                    int n_ = row >> 12, w_ = (row >> 4) & 255, pl = row & 15;
                    int p = ((w_ >> 4) * 4 + (pl >> 2)) * 64 + (w_ & 15) * 4 + (pl & 3);
                    cp = C + ((size_t)n_ * 4096 + p) * 128 + bn + cl;
                } else {
                    cp = C + (size_t)row * ldc + bn + cl;
                }
                float2 v = make_float2(f0, f1);
                if constexpr (EPI == 2 || EPI == 4) {
                    float2 o = *(float2*)cp;
                    v.x += o.x; v.y += o.y;
                }
                if constexpr (EPI == 6) {
                    float2 o = *(const float2*)(R + (size_t)row * ldc + bn + cl);
                    v.x += o.x; v.y += o.y;
                }
                *(float2*)cp = v;
            }
        }
    }
}

// ===========================================================================
// attention 1: per window (16 tokens, 2 heads, hd=64). X += attn(V)
// ===========================================================================
__global__ void attn1_kernel(const float* __restrict__ QKV, float* __restrict__ X) {
    __shared__ float q[16][384];
    __shared__ float s[2][16][16];
    int w = blockIdx.x, tid = threadIdx.x;
    size_t base = (size_t)w * 16 * 384;
    for (int i = tid; i < 16 * 384; i += 128) q[i / 384][i % 384] = QKV[base + i];
    __syncthreads();
    for (int idx = tid; idx < 512; idx += 128) {
        int h = idx >> 8, t1 = (idx >> 4) & 15, t2 = idx & 15;
        const float* qp = &q[t1][h * 64];
        const float* kp = &q[t2][128 + h * 64];
        float a = 0.f;
#pragma unroll
        for (int c = 0; c < 64; c++) a = fmaf(qp[c], kp[c], a);
        s[h][t1][t2] = a * 0.08838834764831843f;
    }
    __syncthreads();
    if (tid < 32) {
        int h = tid >> 4, t1 = tid & 15;
        float m = -1e30f;
#pragma unroll
        for (int j = 0; j < 16; j++) m = fmaxf(m, s[h][t1][j]);
        float sum = 0.f;
#pragma unroll
        for (int j = 0; j < 16; j++) { float e = expf(s[h][t1][j] - m); s[h][t1][j] = e; sum += e; }
        float inv = 1.f / sum;
#pragma unroll
        for (int j = 0; j < 16; j++) s[h][t1][j] *= inv;
    }
    __syncthreads();
    for (int idx = tid; idx < 2048; idx += 128) {
        int t1 = idx >> 7, ch = idx & 127, h = ch >> 6;
        float a = 0.f;
#pragma unroll
        for (int j = 0; j < 16; j++) a = fmaf(s[h][t1][j], q[j][256 + ch], a);
        X[(size_t)(w * 16 + t1) * 128 + ch] += a;
    }
}

// ===========================================================================
// attn2 helpers (R8 path)
// ===========================================================================
__global__ void vt_kernel(const float* __restrict__ QKV, float* __restrict__ Vt) {
    __shared__ float t[32][65];
    int blh = blockIdx.x, g0 = blockIdx.y * 32;
    int b = blh >> 5, l = (blh >> 1) & 15, h = blh & 1;
    int tid = threadIdx.x;
#pragma unroll
    for (int it = 0; it < 8; it++) {
        int e = tid + it * 256;
        int g = e >> 6, c = e & 63;
        t[g][c] = QKV[((size_t)((b * 256 + g0 + g) * 16 + l)) * 384 + 256 + h * 64 + c];
    }
    __syncthreads();
    float* vp = Vt + (size_t)blh * 16384;
#pragma unroll
    for (int it = 0; it < 8; it++) {
        int e = tid + it * 256;
        int c = e >> 5, g = e & 31;
        vp[(size_t)c * 256 + g0 + g] = t[g][c];
    }
}

__global__ void softmax_s(float* __restrict__ S) {
    int row = blockIdx.x * 8 + (threadIdx.x >> 5);
    int lane = threadIdx.x & 31;
    float* r = S + (size_t)row * 256;
    float v[8];
#pragma unroll
    for (int i = 0; i < 8; i++) v[i] = r[lane + i * 32];
    float m = -1e30f;
#pragma unroll
    for (int i = 0; i < 8; i++) m = fmaxf(m, v[i]);
#pragma unroll
    for (int o = 16; o; o >>= 1) m = fmaxf(m, __shfl_xor_sync(0xffffffffu, m, o));
    float s = 0.f;
#pragma unroll
    for (int i = 0; i < 8; i++) { v[i] = expf(v[i] - m); s += v[i]; }
#pragma unroll
    for (int o = 16; o; o >>= 1) s += __shfl_xor_sync(0xffffffffu, s, o);
    float inv = 1.f / s;
#pragma unroll
    for (int i = 0; i < 8; i++) r[lane + i * 32] = v[i] * inv;
}

// ===========================================================================
// persistent ConvLSTM: 128 co-resident blocks, software grid barrier.
// Per step: GEMM phase (block = (bn,bm) tile, identical math to R8's
// per-step gemm) -> barrier -> pointwise phase (block owns 32 pixels,
// coalesced out writes via smem pane) -> barrier.
// ===========================================================================
__device__ __forceinline__ void grid_barrier(int target) {
    __syncthreads();
    if (threadIdx.x == 0) {
        __threadfence();
        atomicAdd(&g_bar, 1);
        while (atomicAdd(&g_bar, 0) < target) { }
    }
    __syncthreads();
}

__global__ void __launch_bounds__(256) lstm_persist(
        const float* __restrict__ Xr, const float* __restrict__ Wl,
        const float* __restrict__ bias,
        float* __restrict__ h, float* __restrict__ c,
        float* __restrict__ gates, float* __restrict__ out) {
    extern __shared__ __align__(16) uint32_t stg[];   // 2 x 256*36 u32
    __shared__ float ht[32 * 129];
    __shared__ float sbias[128];

    const int tid = threadIdx.x, wid = tid >> 5, lane = tid & 31;
    const int blk = blockIdx.x;
    const int bn = blk & 3, bm = blk >> 2;
    const int P0 = bm * 128;          // gemm row tile
    const int q0 = blk * 32;          // pointwise pixel tile
    const int wm0 = (wid & 1) * 64;
    const int wn0 = (wid >> 1) * 32;
    const int srow = tid >> 3, scol = tid & 7;
    constexpr int BUF = 256 * 36;

    if (tid < 128) sbias[tid] = bias[bn * 128 + tid];
    int barcnt = 0;

    for (int n = 0; n < 16; n++) {
        // ============ GEMM phase: gates[P0..+128][bn*128..+128] ============
        const float* Xn = Xr + (size_t)n * NPIX * 128;
        float acc[4][4][4];
#pragma unroll
        for (int mi = 0; mi < 4; mi++)
#pragma unroll
            for (int ni = 0; ni < 4; ni++)
#pragma unroll
                for (int q = 0; q < 4; q++) acc[mi][ni][q] = 0.f;

        float4 aReg[4], bReg[4];
        auto ldg = [&](int k0) {
#pragma unroll
            for (int it = 0; it < 4; it++) {
                int row = P0 + it * 32 + srow;
                if (k0 < 128)
                    aReg[it] = *(const float4*)&Xn[(size_t)row * 128 + k0 + scol * 4];
                else
                    aReg[it] = __ldcg((const float4*)&h[(size_t)row * 128 + (k0 - 128) + scol * 4]);
            }
#pragma unroll
            for (int it = 0; it < 4; it++)
                bReg[it] = *(const float4*)&Wl[(size_t)(bn * 128 + it * 32 + srow) * 256 + k0 + scol * 4];
        };
        auto sts = [&](int buf) {
            uint32_t* base = stg + buf * BUF;
#pragma unroll
            for (int it = 0; it < 4; it++) {
                float4 v = aReg[it];
                uint4 u = make_uint4(f2tf32(v.x), f2tf32(v.y), f2tf32(v.z), f2tf32(v.w));
                *(uint4*)&base[(it * 32 + srow) * 36 + scol * 4] = u;
            }
            uint32_t* bb = base + 128 * 36;
#pragma unroll
            for (int it = 0; it < 4; it++) {
                float4 v = bReg[it];
                uint4 u = make_uint4(f2tf32(v.x), f2tf32(v.y), f2tf32(v.z), f2tf32(v.w));
                *(uint4*)&bb[(it * 32 + srow) * 36 + scol * 4] = u;
            }
        };
        auto compute = [&](int buf) {
            const uint32_t* Ab = stg + buf * BUF;
            const uint32_t* Bb = Ab + 128 * 36;
#pragma unroll
            for (int ks = 0; ks < 4; ks++) {
                int kq = ks * 8 + (lane & 3);
                uint32_t afr[4][4];
#pragma unroll
                for (int mi = 0; mi < 4; mi++) {
                    int r = wm0 + mi * 16 + (lane >> 2);
                    afr[mi][0] = Ab[r * 36 + kq];
                    afr[mi][1] = Ab[(r + 8) * 36 + kq];
                    afr[mi][2] = Ab[r * 36 + kq + 4];
                    afr[mi][3] = Ab[(r + 8) * 36 + kq + 4];
                }
                uint32_t bfr[4][2];
#pragma unroll
                for (int ni = 0; ni < 4; ni++) {
                    int nn = wn0 + ni * 8 + (lane >> 2);
                    bfr[ni][0] = Bb[nn * 36 + kq];
                    bfr[ni][1] = Bb[nn * 36 + kq + 4];
                }
#pragma unroll
                for (int mi = 0; mi < 4; mi++)
#pragma unroll
                    for (int ni = 0; ni < 4; ni++)
                        mma_tf32(acc[mi][ni], afr[mi], bfr[ni]);
            }
        };

        ldg(0);
        sts(0);
        int cur = 0;
        for (int ch = 0; ch < 8; ch++) {
            __syncthreads();
            if (ch + 1 < 8) ldg((ch + 1) << 5);
            compute(cur);
            if (ch + 1 < 8) sts(cur ^ 1);
            cur ^= 1;
        }
#pragma unroll
        for (int mi = 0; mi < 4; mi++) {
#pragma unroll
            for (int ni = 0; ni < 4; ni++) {
#pragma unroll
                for (int half = 0; half < 2; half++) {
                    int row = wm0 + mi * 16 + (lane >> 2) + half * 8;
                    int cl = wn0 + ni * 8 + 2 * (lane & 3);
                    float2 v = make_float2(acc[mi][ni][half * 2 + 0] + sbias[cl],
                                           acc[mi][ni][half * 2 + 1] + sbias[cl + 1]);
                    *(float2*)&gates[(size_t)(P0 + row) * 512 + bn * 128 + cl] = v;
                }
            }
        }
        grid_barrier(128 * (++barcnt));

        // ============ pointwise phase: pixels [q0, q0+32) ============
#pragma unroll 1
        for (int it = 0; it < 4; it++) {
            int pl = wid * 4 + it;
            int p = q0 + pl;
            const float* gp = gates + (size_t)p * 512;
            float fv[4], iv[4], sv[4], ov[4];
#pragma unroll
            for (int j = 0; j < 4; j++) {
                int ch = lane + j * 32;
                fv[j] = __ldcg(gp + ch);        iv[j] = __ldcg(gp + 128 + ch);
                sv[j] = __ldcg(gp + 256 + ch);  ov[j] = __ldcg(gp + 384 + ch);
            }
            float mf = fmaxf(fmaxf(fv[0], fv[1]), fmaxf(fv[2], fv[3]));
            float mi = fmaxf(fmaxf(iv[0], iv[1]), fmaxf(iv[2], iv[3]));
            float mo = fmaxf(fmaxf(ov[0], ov[1]), fmaxf(ov[2], ov[3]));
#pragma unroll
            for (int o = 16; o; o >>= 1) {
                mf = fmaxf(mf, __shfl_xor_sync(0xffffffffu, mf, o));
                mi = fmaxf(mi, __shfl_xor_sync(0xffffffffu, mi, o));
                mo = fmaxf(mo, __shfl_xor_sync(0xffffffffu, mo, o));
            }
            float sf = 0.f, si = 0.f, so = 0.f;
#pragma unroll
            for (int j = 0; j < 4; j++) {
                fv[j] = expf(fv[j] - mf); sf += fv[j];
                iv[j] = expf(iv[j] - mi); si += iv[j];
                ov[j] = expf(ov[j] - mo); so += ov[j];
            }
#pragma unroll
            for (int o = 16; o; o >>= 1) {
                sf += __shfl_xor_sync(0xffffffffu, sf, o);
                si += __shfl_xor_sync(0xffffffffu, si, o);
                so += __shfl_xor_sync(0xffffffffu, so, o);
            }
            float rf = 1.f / sf, ri = 1.f / si, ro = 1.f / so;
#pragma unroll
            for (int j = 0; j < 4; j++) {
                int ch = lane + j * 32;
                float cc = c[(size_t)p * 128 + ch];      // block-private
                float cn = fv[j] * rf * cc + iv[j] * ri * tanhf(sv[j]);
                float hn = ov[j] * ro * tanhf(cn);
                c[(size_t)p * 128 + ch] = cn;
                h[(size_t)p * 128 + ch] = hn;
                ht[pl * 129 + ch] = hn;
            }
        }
        __syncthreads();
        // coalesced out[n] write (and hf at n==15)
        for (int i = tid; i < 4096; i += 256) {
            int ch = i >> 5, pl = i & 31;
            float hv = ht[pl * 129 + ch];
            out[((size_t)(n * 128 + ch)) * 4096 + q0 + pl] = hv;
            if (n == 15) out[((size_t)(16 * 128 + ch)) * 4096 + q0 + pl] = hv;
        }
        if (n == 15) {
            __syncthreads();
            for (int i = tid; i < 4096; i += 256) {
                int ch = i >> 5, pl = i & 31;
                ht[pl * 129 + ch] = c[(size_t)(q0 + pl) * 128 + ch];
            }
            __syncthreads();
            for (int i = tid; i < 4096; i += 256) {
                int ch = i >> 5, pl = i & 31;
                out[((size_t)(17 * 128 + ch)) * 4096 + q0 + pl] = ht[pl * 129 + ch];
            }
        }
        grid_barrier(128 * (++barcnt));
    }
}

// ===========================================================================
extern "C" void kernel_launch(void* const* d_in, const int* in_sizes, int n_in,
                              void* d_out, int out_size) {
    const float* x       = (const float*)d_in[0];
    const float* h0      = (const float*)d_in[1];
    const float* c0      = (const float*)d_in[2];
    const float* conv_w  = (const float*)d_in[3];
    const float* conv_b  = (const float*)d_in[4];
    const float* qkv1_w  = (const float*)d_in[5];
    const float* qkv1_b  = (const float*)d_in[6];
    const float* mlp1_w1 = (const float*)d_in[7];
    const float* mlp1_b1 = (const float*)d_in[8];
    const float* mlp1_w2 = (const float*)d_in[9];
    const float* mlp1_b2 = (const float*)d_in[10];
    const float* qkv2_w  = (const float*)d_in[11];
    const float* qkv2_b  = (const float*)d_in[12];
    const float* mlp2_w1 = (const float*)d_in[13];
    const float* mlp2_b1 = (const float*)d_in[14];
    const float* mlp2_w2 = (const float*)d_in[15];
    const float* mlp2_b2 = (const float*)d_in[16];
    const float* lstm_wx = (const float*)d_in[17];
    const float* lstm_wh = (const float*)d_in[18];
    const float* lstm_bh = (const float*)d_in[19];
    float* out = (float*)d_out;
    (void)in_sizes; (void)n_in; (void)out_size;

    float *X, *QKV, *Hid, *Xr, *Vt, *h, *c, *gates, *Wc, *Wl;
    cudaGetSymbolAddress((void**)&X, g_X);
    cudaGetSymbolAddress((void**)&QKV, g_QKV);
    cudaGetSymbolAddress((void**)&Hid, g_Hid);
    cudaGetSymbolAddress((void**)&Xr, g_Xr);
    cudaGetSymbolAddress((void**)&Vt, g_Vt);
    cudaGetSymbolAddress((void**)&h, g_h);
    cudaGetSymbolAddress((void**)&c, g_c);
    cudaGetSymbolAddress((void**)&gates, g_gates);
    cudaGetSymbolAddress((void**)&Wc, g_Wc);
    cudaGetSymbolAddress((void**)&Wl, g_Wl);

    const int SM128 = 2 * (128 + 128) * 36 * 4;                 // 73728
    const int SM64  = 2 * (128 + 64) * 36 * 4;                  // 55296
    cudaFuncSetAttribute((const void*)mma_gemm<1, 0, 128>, cudaFuncAttributeMaxDynamicSharedMemorySize, SM128);
    cudaFuncSetAttribute((const void*)mma_gemm<0, 0, 128>, cudaFuncAttributeMaxDynamicSharedMemorySize, SM128);
    cudaFuncSetAttribute((const void*)mma_gemm<0, 1, 128>, cudaFuncAttributeMaxDynamicSharedMemorySize, SM128);
    cudaFuncSetAttribute((const void*)mma_gemm<0, 2, 128>, cudaFuncAttributeMaxDynamicSharedMemorySize, SM128);
    cudaFuncSetAttribute((const void*)mma_gemm<0, 6, 128>, cudaFuncAttributeMaxDynamicSharedMemorySize, SM128);
    cudaFuncSetAttribute((const void*)mma_gemm<3, 3, 128>, cudaFuncAttributeMaxDynamicSharedMemorySize, SM128);
    cudaFuncSetAttribute((const void*)mma_gemm<4, 4, 64>,  cudaFuncAttributeMaxDynamicSharedMemorySize, SM64);
    cudaFuncSetAttribute((const void*)lstm_persist, cudaFuncAttributeMaxDynamicSharedMemorySize, SM128);

    prep_convw<<<512, 128>>>(conv_w, Wc);
    prep_lstmw<<<1024, 128>>>(lstm_wx, lstm_wh, Wl);
    init_hc<<<4096, 128>>>(h0, c0, h, c);
    transpose_x<<<32768, 256>>>(x, Hid);

    // conv as implicit-im2col GEMM
    mma_gemm<1, 0, 128><<<dim3(1, 512), 256, SM128>>>(Hid, 0, Wc, 512, conv_b, nullptr, X, 128, 512);

    // LocalMSA
    mma_gemm<0, 0, 128><<<dim3(3, 512), 256, SM128>>>(X, 128, qkv1_w, 128, qkv1_b, nullptr, QKV, 384, 128);
    attn1_kernel<<<NWIN, 128>>>(QKV, X);
    // MLP1
    mma_gemm<0, 1, 128><<<dim3(4, 512), 256, SM128>>>(X, 128, mlp1_w1, 128, mlp1_b1, nullptr, Hid, 512, 128);
    mma_gemm<0, 2, 128><<<dim3(1, 512), 256, SM128>>>(Hid, 512, mlp1_w2, 512, mlp1_b2, nullptr, X, 128, 512);

    // DilatedMSA (R8 path)
    mma_gemm<0, 0, 128><<<dim3(3, 512), 256, SM128>>>(X, 128, qkv2_w, 128, qkv2_b, nullptr, QKV, 384, 128);
    vt_kernel<<<dim3(512, 8), 256>>>(QKV, Vt);
    mma_gemm<3, 3, 128><<<dim3(2, 2, 512), 256, SM128>>>(QKV, 0, QKV, 0, nullptr, nullptr, Hid, 256, 64);
    softmax_s<<<16384, 256>>>(Hid);
    mma_gemm<4, 4, 64><<<dim3(1, 2, 512), 256, SM64>>>(Hid, 256, Vt, 256, nullptr, nullptr, X, 128, 256);
    // MLP2 (second GEMM fuses residual + window-reverse scatter into Xr)
    mma_gemm<0, 1, 128><<<dim3(4, 512), 256, SM128>>>(X, 128, mlp2_w1, 128, mlp2_b1, nullptr, Hid, 512, 128);
    mma_gemm<0, 6, 128><<<dim3(1, 512), 256, SM128>>>(Hid, 512, mlp2_w2, 512, mlp2_b2, X, Xr, 128, 512);

    // persistent ConvLSTM scan (single kernel, software grid barriers)
    lstm_persist<<<128, 256, SM128>>>(Xr, Wl, lstm_bh, h, c, gates, out);
}

// round 12
// speedup vs baseline: 1.0764x; 1.0047x over previous
#include <cuda_runtime.h>
#include <cuda_bf16.h>
#include <cstdint>
#include <math.h>

// ===========================================================================
#define T_TOK   65536
#define NWIN    4096
#define NPIX    4096

// scratch (device globals)
__device__ float g_X  [T_TOK * 128];
__device__ float g_QKV[T_TOK * 384];
__device__ float g_Hid[(size_t)T_TOK * 512];   // NHWC x / mlp hidden / attn S
__device__ float g_Xr [T_TOK * 128];
__device__ float g_Vt [512 * 64 * 256];
__device__ float g_h  [NPIX * 128];
__device__ float g_c  [NPIX * 128];
__device__ float g_gates[NPIX * 512];
__device__ float g_Wc [128 * 512];
__device__ float g_Wl [512 * 256];
__device__ float g_stats[131072 * 2];          // per-S-row (max, 1/sum)
__device__ int   g_bar;

__device__ __forceinline__ uint32_t f2tf32(float f) {
    uint32_t u; asm("cvt.rna.tf32.f32 %0, %1;" : "=r"(u) : "f"(f)); return u;
}
__device__ __forceinline__ void mma_tf32(float* c, const uint32_t* a, const uint32_t* b) {
    asm volatile(
        "mma.sync.aligned.m16n8k8.row.col.f32.tf32.tf32.f32 "
        "{%0,%1,%2,%3}, {%4,%5,%6,%7}, {%8,%9}, {%0,%1,%2,%3};"
        : "+f"(c[0]), "+f"(c[1]), "+f"(c[2]), "+f"(c[3])
        : "r"(a[0]), "r"(a[1]), "r"(a[2]), "r"(a[3]), "r"(b[0]), "r"(b[1]));
}

// ===========================================================================
// merged prep kernel: conv weight reorder + lstm weight concat + h/c init
// ===========================================================================
__global__ void prep_all(const float* __restrict__ cw, float* __restrict__ Wc,
                         const float* __restrict__ wx, const float* __restrict__ wh,
                         float* __restrict__ Wl,
                         const float* __restrict__ h0, const float* __restrict__ c0,
                         float* __restrict__ h, float* __restrict__ c) {
    int idx = blockIdx.x * 128 + threadIdx.x;         // 4096*128 = 524288
    if (idx == 0) g_bar = 0;
    if (idx < 65536) {
        int o = idx >> 9, rem = idx & 511, tap = rem >> 7, i = rem & 127;
        Wc[idx] = cw[o * 512 + i * 4 + tap];
    }
    if (idx < 131072) {
        int o = idx >> 8, k = idx & 255;
        Wl[idx] = (k < 128) ? wx[o * 128 + k] : wh[o * 128 + (k - 128)];
    }
    {
        int ch = idx >> 12, p = idx & 4095;
        h[p * 128 + ch] = h0[idx];
        c[p * 128 + ch] = c0[idx];
    }
}

// NCHW -> NHWC transpose of x (output 33.5M floats -> g_Hid)
__global__ void transpose_x(const float* __restrict__ x, float* __restrict__ xt) {
    __shared__ float t[32][33];
    int bid = blockIdx.x;
    int tile = bid & 15, by = bid >> 4;
    int i0 = (tile >> 2) * 32, x0 = (tile & 3) * 32;
    int tx = threadIdx.x & 31, ty = threadIdx.x >> 5;
    const float* xin = x + (size_t)(by >> 7) * 2097152 + (size_t)(by & 127) * 128;
#pragma unroll
    for (int k = 0; k < 4; k++)
        t[ty + k * 8][tx] = xin[(size_t)(i0 + ty + k * 8) * 16384 + x0 + tx];
    __syncthreads();
    float* xout = xt + (size_t)by * 16384;
#pragma unroll
    for (int k = 0; k < 4; k++)
        xout[(size_t)(x0 + ty + k * 8) * 128 + i0 + tx] = t[tx][ty + k * 8];
}

// ===========================================================================
// generic mma.sync tf32 GEMM, double-buffered (R8/R11 version).
// MODE: 0 plain | 1 conv-im2col A | 3 attn QK^T | 4 attn PV | 5 attn PV + inline softmax
// EPI: 0 bias | 1 bias+gelu | 2 bias+add-in-place | 3 scale | 4 add-in-place
//      6 bias + add-R + scatter window-reverse
// For MODE==5, R carries the per-row (max, inv_sum) stats pointer.
// ===========================================================================
template<int MODE>
__device__ __forceinline__ const float* a_ptr(const float* A, int lda,
                                              int m, int k0, int blh) {
    if constexpr (MODE == 1) {
        int w = m >> 4, pl = m & 15;
        int b = w >> 8, yg = (w >> 4) & 15, xg = w & 15;
        int yl = pl >> 2, xl = pl & 3;
        int tap = k0 >> 7, ky = tap >> 1, kx = tap & 1;
        int Y = yg * 8 + yl * 2 + ky, XX = xg * 8 + xl * 2 + kx;
        return A + ((size_t)(b * 128 + Y) * 128 + XX) * 128 + (k0 & 127);
    } else if constexpr (MODE == 3) {
        int b = blh >> 5, l = (blh >> 1) & 15, h = blh & 1;
        return A + ((size_t)((b * 256 + m) * 16 + l)) * 384 + h * 64 + k0;
    } else if constexpr (MODE == 4 || MODE == 5) {
        return A + (size_t)blh * 65536 + (size_t)m * 256 + k0;
    } else {
        return A + (size_t)m * lda + k0;
    }
}
template<int MODE>
__device__ __forceinline__ const float* b_ptr(const float* B, int ldb, int n, int k0, int blh) {
    if constexpr (MODE == 3) {
        int b = blh >> 5, l = (blh >> 1) & 15, h = blh & 1;
        return B + ((size_t)((b * 256 + n) * 16 + l)) * 384 + 128 + h * 64 + k0;
    } else if constexpr (MODE == 4 || MODE == 5) {
        return B + (size_t)blh * 16384 + (size_t)n * 256 + k0;
    } else {
        return B + (size_t)n * ldb + k0;
    }
}

__device__ __forceinline__ float gelu_exact(float v) {
    return 0.5f * v * (1.0f + erff(v * 0.70710678118654752f));
}

template<int MODE, int EPI, int NT>
__global__ void __launch_bounds__(256) mma_gemm(
        const float* __restrict__ A, int lda,
        const float* __restrict__ B, int ldb,
        const float* __restrict__ bias, const float* __restrict__ R,
        float* __restrict__ C, int ldc, int K) {
    constexpr int MW = (NT == 128) ? 2 : 4;
    constexpr int NW = 8 / MW;
    constexpr int WM = 128 / MW;
    constexpr int WN = NT / NW;
    constexpr int MI = WM / 16;
    constexpr int NI = WN / 8;
    constexpr int BUF = (128 + NT) * 36;

    extern __shared__ __align__(16) uint32_t sm[];
    __shared__ float sbias[NT];

    const int tid = threadIdx.x, wid = tid >> 5, lane = tid & 31;
    const int bm = blockIdx.y * 128, bn = blockIdx.x * NT;
    const int blh = blockIdx.z;
    const int wm0 = (wid & (MW - 1)) * WM;
    const int wn0 = (wid / MW) * WN;
    const int srow = tid >> 3, scol = tid & 7;

    if (EPI == 0 || EPI == 1 || EPI == 2 || EPI == 6) {
        for (int i = tid; i < NT; i += 256) sbias[i] = bias[bn + i];
    }

    // per-thread softmax stats for the 4 staged A-rows (MODE==5)
    float st_m[4], st_i[4];
    if constexpr (MODE == 5) {
#pragma unroll
        for (int it = 0; it < 4; it++) {
            int gr = blh * 256 + bm + it * 32 + srow;
            st_m[it] = R[gr * 2];
            st_i[it] = R[gr * 2 + 1];
        }
    }

    float acc[MI][NI][4];
#pragma unroll
    for (int mi = 0; mi < MI; mi++)
#pragma unroll
        for (int ni = 0; ni < NI; ni++)
#pragma unroll
            for (int q = 0; q < 4; q++) acc[mi][ni][q] = 0.f;

    float4 aReg[4];
    float4 bReg[NT / 32];

    auto ldg = [&](int k0) {
#pragma unroll
        for (int it = 0; it < 4; it++)
            aReg[it] = ((const float4*)a_ptr<MODE>(A, lda, bm + it * 32 + srow, k0, blh))[scol];
#pragma unroll
        for (int it = 0; it < NT / 32; it++)
            bReg[it] = ((const float4*)b_ptr<MODE>(B, ldb, bn + it * 32 + srow, k0, blh))[scol];
    };
    auto sts = [&](int buf) {
        uint32_t* base = sm + buf * BUF;
#pragma unroll
        for (int it = 0; it < 4; it++) {
            float4 v = aReg[it];
            if constexpr (MODE == 5) {
                v.x = expf(v.x - st_m[it]) * st_i[it];
                v.y = expf(v.y - st_m[it]) * st_i[it];
                v.z = expf(v.z - st_m[it]) * st_i[it];
                v.w = expf(v.w - st_m[it]) * st_i[it];
            }
            uint4 u = make_uint4(f2tf32(v.x), f2tf32(v.y), f2tf32(v.z), f2tf32(v.w));
            *(uint4*)&base[(it * 32 + srow) * 36 + scol * 4] = u;
        }
        uint32_t* bb = base + 128 * 36;
#pragma unroll
        for (int it = 0; it < NT / 32; it++) {
            float4 v = bReg[it];
            uint4 u = make_uint4(f2tf32(v.x), f2tf32(v.y), f2tf32(v.z), f2tf32(v.w));
            *(uint4*)&bb[(it * 32 + srow) * 36 + scol * 4] = u;
        }
    };
    auto compute = [&](int buf) {
        const uint32_t* Ab = sm + buf * BUF;
        const uint32_t* Bb = Ab + 128 * 36;
#pragma unroll
        for (int ks = 0; ks < 4; ks++) {
            int kq = ks * 8 + (lane & 3);
            uint32_t afr[MI][4];
#pragma unroll
            for (int mi = 0; mi < MI; mi++) {
                int r = wm0 + mi * 16 + (lane >> 2);
                afr[mi][0] = Ab[r * 36 + kq];
                afr[mi][1] = Ab[(r + 8) * 36 + kq];
                afr[mi][2] = Ab[r * 36 + kq + 4];
                afr[mi][3] = Ab[(r + 8) * 36 + kq + 4];
            }
            uint32_t bfr[NI][2];
#pragma unroll
            for (int ni = 0; ni < NI; ni++) {
                int n = wn0 + ni * 8 + (lane >> 2);
                bfr[ni][0] = Bb[n * 36 + kq];
                bfr[ni][1] = Bb[n * 36 + kq + 4];
            }
#pragma unroll
            for (int mi = 0; mi < MI; mi++)
#pragma unroll
                for (int ni = 0; ni < NI; ni++)
                    mma_tf32(acc[mi][ni], afr[mi], bfr[ni]);
        }
    };

    const int NCH = K >> 5;
    ldg(0);
    sts(0);
    int cur = 0;
    for (int ch = 0; ch < NCH; ch++) {
        __syncthreads();
        if (ch + 1 < NCH) ldg((ch + 1) << 5);
        compute(cur);
        if (ch + 1 < NCH) sts(cur ^ 1);
        cur ^= 1;
    }

    // ---- epilogue ----
#pragma unroll
    for (int mi = 0; mi < MI; mi++) {
#pragma unroll
        for (int ni = 0; ni < NI; ni++) {
#pragma unroll
            for (int half = 0; half < 2; half++) {
                int row = bm + wm0 + mi * 16 + (lane >> 2) + half * 8;
                int cl = wn0 + ni * 8 + 2 * (lane & 3);
                float f0 = acc[mi][ni][half * 2 + 0];
                float f1 = acc[mi][ni][half * 2 + 1];
                if constexpr (EPI == 0 || EPI == 2 || EPI == 6) { f0 += sbias[cl]; f1 += sbias[cl + 1]; }
                else if constexpr (EPI == 1) { f0 = gelu_exact(f0 + sbias[cl]); f1 = gelu_exact(f1 + sbias[cl + 1]); }
                else if constexpr (EPI == 3) { f0 *= 0.08838834764831843f; f1 *= 0.08838834764831843f; }
                float* cp;
                if constexpr (MODE == 4 || MODE == 5) {
                    int b = blh >> 5, l = (blh >> 1) & 15, h = blh & 1;
                    cp = C + ((size_t)((b * 256 + row) * 16 + l)) * 128 + h * 64 + cl;
                } else if constexpr (MODE == 3) {
                    cp = C + (size_t)blh * 65536 + (size_t)row * 256 + bn + cl;
                } else if constexpr (EPI == 6) {
                    int n_ = row >> 12, w_ = (row >> 4) & 255, pl = row & 15;
                    int p = ((w_ >> 4) * 4 + (pl >> 2)) * 64 + (w_ & 15) * 4 + (pl & 3);
                    cp = C + ((size_t)n_ * 4096 + p) * 128 + bn + cl;
                } else {
                    cp = C + (size_t)row * ldc + bn + cl;
                }
                float2 v = make_float2(f0, f1);
                if constexpr (EPI == 2 || EPI == 4) {
                    float2 o = *(float2*)cp;
                    v.x += o.x; v.y += o.y;
                }
                if constexpr (EPI == 6) {
                    float2 o = *(const float2*)(R + (size_t)row * ldc + bn + cl);
                    v.x += o.x; v.y += o.y;
                }
                *(float2*)cp = v;
            }
        }
    }
}

// ===========================================================================
// attention 1: per window (16 tokens, 2 heads, hd=64). X += attn(V)
// ===========================================================================
__global__ void attn1_kernel(const float* __restrict__ QKV, float* __restrict__ X) {
    __shared__ float q[16][384];
    __shared__ float s[2][16][16];
    int w = blockIdx.x, tid = threadIdx.x;
    size_t base = (size_t)w * 16 * 384;
    for (int i = tid; i < 16 * 384; i += 128) q[i / 384][i % 384] = QKV[base + i];
    __syncthreads();
    for (int idx = tid; idx < 512; idx += 128) {
        int h = idx >> 8, t1 = (idx >> 4) & 15, t2 = idx & 15;
        const float* qp = &q[t1][h * 64];
        const float* kp = &q[t2][128 + h * 64];
        float a = 0.f;
#pragma unroll
        for (int c = 0; c < 64; c++) a = fmaf(qp[c], kp[c], a);
        s[h][t1][t2] = a * 0.08838834764831843f;
    }
    __syncthreads();
    if (tid < 32) {
        int h = tid >> 4, t1 = tid & 15;
        float m = -1e30f;
#pragma unroll
        for (int j = 0; j < 16; j++) m = fmaxf(m, s[h][t1][j]);
        float sum = 0.f;
#pragma unroll
        for (int j = 0; j < 16; j++) { float e = expf(s[h][t1][j] - m); s[h][t1][j] = e; sum += e; }
        float inv = 1.f / sum;
#pragma unroll
        for (int j = 0; j < 16; j++) s[h][t1][j] *= inv;
    }
    __syncthreads();
    for (int idx = tid; idx < 2048; idx += 128) {
        int t1 = idx >> 7, ch = idx & 127, h = ch >> 6;
        float a = 0.f;
#pragma unroll
        for (int j = 0; j < 16; j++) a = fmaf(s[h][t1][j], q[j][256 + ch], a);
        X[(size_t)(w * 16 + t1) * 128 + ch] += a;
    }
}

// ===========================================================================
// attn2 helpers
// ===========================================================================
__global__ void vt_kernel(const float* __restrict__ QKV, float* __restrict__ Vt) {
    __shared__ float t[32][65];
    int blh = blockIdx.x, g0 = blockIdx.y * 32;
    int b = blh >> 5, l = (blh >> 1) & 15, h = blh & 1;
    int tid = threadIdx.x;
#pragma unroll
    for (int it = 0; it < 8; it++) {
        int e = tid + it * 256;
        int g = e >> 6, c = e & 63;
        t[g][c] = QKV[((size_t)((b * 256 + g0 + g) * 16 + l)) * 384 + 256 + h * 64 + c];
    }
    __syncthreads();
    float* vp = Vt + (size_t)blh * 16384;
#pragma unroll
    for (int it = 0; it < 8; it++) {
        int e = tid + it * 256;
        int c = e >> 5, g = e & 31;
        vp[(size_t)c * 256 + g0 + g] = t[g][c];
    }
}

// per-row (max, 1/sum) stats of S — read-only pass, no S rewrite
__global__ void softmax_stats(const float* __restrict__ S, float* __restrict__ st) {
    int row = blockIdx.x * 8 + (threadIdx.x >> 5);
    int lane = threadIdx.x & 31;
    const float* r = S + (size_t)row * 256;
    float v[8];
#pragma unroll
    for (int i = 0; i < 8; i++) v[i] = r[lane + i * 32];
    float m = -1e30f;
#pragma unroll
    for (int i = 0; i < 8; i++) m = fmaxf(m, v[i]);
#pragma unroll
    for (int o = 16; o; o >>= 1) m = fmaxf(m, __shfl_xor_sync(0xffffffffu, m, o));
    float s = 0.f;
#pragma unroll
    for (int i = 0; i < 8; i++) s += expf(v[i] - m);
#pragma unroll
    for (int o = 16; o; o >>= 1) s += __shfl_xor_sync(0xffffffffu, s, o);
    if (lane == 0) {
        st[row * 2]     = m;
        st[row * 2 + 1] = 1.f / s;
    }
}

// ===========================================================================
// persistent ConvLSTM (R11 champion, unchanged)
// ===========================================================================
__device__ __forceinline__ void grid_barrier(int target) {
    __syncthreads();
    if (threadIdx.x == 0) {
        __threadfence();
        atomicAdd(&g_bar, 1);
        while (atomicAdd(&g_bar, 0) < target) { }
    }
    __syncthreads();
}

__global__ void __launch_bounds__(256) lstm_persist(
        const float* __restrict__ Xr, const float* __restrict__ Wl,
        const float* __restrict__ bias,
        float* __restrict__ h, float* __restrict__ c,
        float* __restrict__ gates, float* __restrict__ out) {
    extern __shared__ __align__(16) uint32_t stg[];
    __shared__ float ht[32 * 129];
    __shared__ float sbias[128];

    const int tid = threadIdx.x, wid = tid >> 5, lane = tid & 31;
    const int blk = blockIdx.x;
    const int bn = blk & 3, bm = blk >> 2;
    const int P0 = bm * 128;
    const int q0 = blk * 32;
    const int wm0 = (wid & 1) * 64;
    const int wn0 = (wid >> 1) * 32;
    const int srow = tid >> 3, scol = tid & 7;
    constexpr int BUF = 256 * 36;

    if (tid < 128) sbias[tid] = bias[bn * 128 + tid];
    int barcnt = 0;

    for (int n = 0; n < 16; n++) {
        const float* Xn = Xr + (size_t)n * NPIX * 128;
        float acc[4][4][4];
#pragma unroll
        for (int mi = 0; mi < 4; mi++)
#pragma unroll
            for (int ni = 0; ni < 4; ni++)
#pragma unroll
                for (int q = 0; q < 4; q++) acc[mi][ni][q] = 0.f;

        float4 aReg[4], bReg[4];
        auto ldg = [&](int k0) {
#pragma unroll
            for (int it = 0; it < 4; it++) {
                int row = P0 + it * 32 + srow;
                if (k0 < 128)
                    aReg[it] = *(const float4*)&Xn[(size_t)row * 128 + k0 + scol * 4];
                else
                    aReg[it] = __ldcg((const float4*)&h[(size_t)row * 128 + (k0 - 128) + scol * 4]);
            }
#pragma unroll
            for (int it = 0; it < 4; it++)
                bReg[it] = *(const float4*)&Wl[(size_t)(bn * 128 + it * 32 + srow) * 256 + k0 + scol * 4];
        };
        auto sts = [&](int buf) {
            uint32_t* base = stg + buf * BUF;
#pragma unroll
            for (int it = 0; it < 4; it++) {
                float4 v = aReg[it];
                uint4 u = make_uint4(f2tf32(v.x), f2tf32(v.y), f2tf32(v.z), f2tf32(v.w));
                *(uint4*)&base[(it * 32 + srow) * 36 + scol * 4] = u;
            }
            uint32_t* bb = base + 128 * 36;
#pragma unroll
            for (int it = 0; it < 4; it++) {
                float4 v = bReg[it];
                uint4 u = make_uint4(f2tf32(v.x), f2tf32(v.y), f2tf32(v.z), f2tf32(v.w));
                *(uint4*)&bb[(it * 32 + srow) * 36 + scol * 4] = u;
            }
        };
        auto compute = [&](int buf) {
            const uint32_t* Ab = stg + buf * BUF;
            const uint32_t* Bb = Ab + 128 * 36;
#pragma unroll
            for (int ks = 0; ks < 4; ks++) {
                int kq = ks * 8 + (lane & 3);
                uint32_t afr[4][4];
#pragma unroll
                for (int mi = 0; mi < 4; mi++) {
                    int r = wm0 + mi * 16 + (lane >> 2);
                    afr[mi][0] = Ab[r * 36 + kq];
                    afr[mi][1] = Ab[(r + 8) * 36 + kq];
                    afr[mi][2] = Ab[r * 36 + kq + 4];
                    afr[mi][3] = Ab[(r + 8) * 36 + kq + 4];
                }
                uint32_t bfr[4][2];
#pragma unroll
                for (int ni = 0; ni < 4; ni++) {
                    int nn = wn0 + ni * 8 + (lane >> 2);
                    bfr[ni][0] = Bb[nn * 36 + kq];
                    bfr[ni][1] = Bb[nn * 36 + kq + 4];
                }
#pragma unroll
                for (int mi = 0; mi < 4; mi++)
#pragma unroll
                    for (int ni = 0; ni < 4; ni++)
                        mma_tf32(acc[mi][ni], afr[mi], bfr[ni]);
            }
        };

        ldg(0);
        sts(0);
        int cur = 0;
        for (int ch = 0; ch < 8; ch++) {
            __syncthreads();
            if (ch + 1 < 8) ldg((ch + 1) << 5);
            compute(cur);
            if (ch + 1 < 8) sts(cur ^ 1);
            cur ^= 1;
        }
#pragma unroll
        for (int mi = 0; mi < 4; mi++) {
#pragma unroll
            for (int ni = 0; ni < 4; ni++) {
#pragma unroll
                for (int half = 0; half < 2; half++) {
                    int row = wm0 + mi * 16 + (lane >> 2) + half * 8;
                    int cl = wn0 + ni * 8 + 2 * (lane & 3);
                    float2 v = make_float2(acc[mi][ni][half * 2 + 0] + sbias[cl],
                                           acc[mi][ni][half * 2 + 1] + sbias[cl + 1]);
                    *(float2*)&gates[(size_t)(P0 + row) * 512 + bn * 128 + cl] = v;
                }
            }
        }
        grid_barrier(128 * (++barcnt));

#pragma unroll 1
        for (int it = 0; it < 4; it++) {
            int pl = wid * 4 + it;
            int p = q0 + pl;
            const float* gp = gates + (size_t)p * 512;
            float fv[4], iv[4], sv[4], ov[4];
#pragma unroll
            for (int j = 0; j < 4; j++) {
                int ch = lane + j * 32;
                fv[j] = __ldcg(gp + ch);        iv[j] = __ldcg(gp + 128 + ch);
                sv[j] = __ldcg(gp + 256 + ch);  ov[j] = __ldcg(gp + 384 + ch);
            }
            float mf = fmaxf(fmaxf(fv[0], fv[1]), fmaxf(fv[2], fv[3]));
            float mi = fmaxf(fmaxf(iv[0], iv[1]), fmaxf(iv[2], iv[3]));
            float mo = fmaxf(fmaxf(ov[0], ov[1]), fmaxf(ov[2], ov[3]));
#pragma unroll
            for (int o = 16; o; o >>= 1) {
                mf = fmaxf(mf, __shfl_xor_sync(0xffffffffu, mf, o));
                mi = fmaxf(mi, __shfl_xor_sync(0xffffffffu, mi, o));
                mo = fmaxf(mo, __shfl_xor_sync(0xffffffffu, mo, o));
            }
            float sf = 0.f, si = 0.f, so = 0.f;
#pragma unroll
            for (int j = 0; j < 4; j++) {
                fv[j] = expf(fv[j] - mf); sf += fv[j];
                iv[j] = expf(iv[j] - mi); si += iv[j];
                ov[j] = expf(ov[j] - mo); so += ov[j];
            }
#pragma unroll
            for (int o = 16; o; o >>= 1) {
                sf += __shfl_xor_sync(0xffffffffu, sf, o);
                si += __shfl_xor_sync(0xffffffffu, si, o);
                so += __shfl_xor_sync(0xffffffffu, so, o);
            }
            float rf = 1.f / sf, ri = 1.f / si, ro = 1.f / so;
#pragma unroll
            for (int j = 0; j < 4; j++) {
                int ch = lane + j * 32;
                float cc = c[(size_t)p * 128 + ch];
                float cn = fv[j] * rf * cc + iv[j] * ri * tanhf(sv[j]);
                float hn = ov[j] * ro * tanhf(cn);
                c[(size_t)p * 128 + ch] = cn;
                h[(size_t)p * 128 + ch] = hn;
                ht[pl * 129 + ch] = hn;
            }
        }
        __syncthreads();
        for (int i = tid; i < 4096; i += 256) {
            int ch = i >> 5, pl = i & 31;
            float hv = ht[pl * 129 + ch];
            out[((size_t)(n * 128 + ch)) * 4096 + q0 + pl] = hv;
            if (n == 15) out[((size_t)(16 * 128 + ch)) * 4096 + q0 + pl] = hv;
        }
        if (n == 15) {
            __syncthreads();
            for (int i = tid; i < 4096; i += 256) {
                int ch = i >> 5, pl = i & 31;
                ht[pl * 129 + ch] = c[(size_t)(q0 + pl) * 128 + ch];
            }
            __syncthreads();
            for (int i = tid; i < 4096; i += 256) {
                int ch = i >> 5, pl = i & 31;
                out[((size_t)(17 * 128 + ch)) * 4096 + q0 + pl] = ht[pl * 129 + ch];
            }
        }
        grid_barrier(128 * (++barcnt));
    }
}

// ===========================================================================
extern "C" void kernel_launch(void* const* d_in, const int* in_sizes, int n_in,
                              void* d_out, int out_size) {
    const float* x       = (const float*)d_in[0];
    const float* h0      = (const float*)d_in[1];
    const float* c0      = (const float*)d_in[2];
    const float* conv_w  = (const float*)d_in[3];
    const float* conv_b  = (const float*)d_in[4];
    const float* qkv1_w  = (const float*)d_in[5];
    const float* qkv1_b  = (const float*)d_in[6];
    const float* mlp1_w1 = (const float*)d_in[7];
    const float* mlp1_b1 = (const float*)d_in[8];
    const float* mlp1_w2 = (const float*)d_in[9];
    const float* mlp1_b2 = (const float*)d_in[10];
    const float* qkv2_w  = (const float*)d_in[11];
    const float* qkv2_b  = (const float*)d_in[12];
    const float* mlp2_w1 = (const float*)d_in[13];
    const float* mlp2_b1 = (const float*)d_in[14];
    const float* mlp2_w2 = (const float*)d_in[15];
    const float* mlp2_b2 = (const float*)d_in[16];
    const float* lstm_wx = (const float*)d_in[17];
    const float* lstm_wh = (const float*)d_in[18];
    const float* lstm_bh = (const float*)d_in[19];
    float* out = (float*)d_out;
    (void)in_sizes; (void)n_in; (void)out_size;

    float *X, *QKV, *Hid, *Xr, *Vt, *h, *c, *gates, *Wc, *Wl, *stats;
    cudaGetSymbolAddress((void**)&X, g_X);
    cudaGetSymbolAddress((void**)&QKV, g_QKV);
    cudaGetSymbolAddress((void**)&Hid, g_Hid);
    cudaGetSymbolAddress((void**)&Xr, g_Xr);
    cudaGetSymbolAddress((void**)&Vt, g_Vt);
    cudaGetSymbolAddress((void**)&h, g_h);
    cudaGetSymbolAddress((void**)&c, g_c);
    cudaGetSymbolAddress((void**)&gates, g_gates);
    cudaGetSymbolAddress((void**)&Wc, g_Wc);
    cudaGetSymbolAddress((void**)&Wl, g_Wl);
    cudaGetSymbolAddress((void**)&stats, g_stats);

    const int SM128 = 2 * (128 + 128) * 36 * 4;                 // 73728
    const int SM64  = 2 * (128 + 64) * 36 * 4;                  // 55296
    cudaFuncSetAttribute((const void*)mma_gemm<1, 0, 128>, cudaFuncAttributeMaxDynamicSharedMemorySize, SM128);
    cudaFuncSetAttribute((const void*)mma_gemm<0, 0, 128>, cudaFuncAttributeMaxDynamicSharedMemorySize, SM128);
    cudaFuncSetAttribute((const void*)mma_gemm<0, 1, 128>, cudaFuncAttributeMaxDynamicSharedMemorySize, SM128);
    cudaFuncSetAttribute((const void*)mma_gemm<0, 2, 128>, cudaFuncAttributeMaxDynamicSharedMemorySize, SM128);
    cudaFuncSetAttribute((const void*)mma_gemm<0, 6, 128>, cudaFuncAttributeMaxDynamicSharedMemorySize, SM128);
    cudaFuncSetAttribute((const void*)mma_gemm<3, 3, 128>, cudaFuncAttributeMaxDynamicSharedMemorySize, SM128);
    cudaFuncSetAttribute((const void*)mma_gemm<5, 4, 64>,  cudaFuncAttributeMaxDynamicSharedMemorySize, SM64);
    cudaFuncSetAttribute((const void*)lstm_persist, cudaFuncAttributeMaxDynamicSharedMemorySize, SM128);

    prep_all<<<4096, 128>>>(conv_w, Wc, lstm_wx, lstm_wh, Wl, h0, c0, h, c);
    transpose_x<<<32768, 256>>>(x, Hid);

    // conv as implicit-im2col GEMM
    mma_gemm<1, 0, 128><<<dim3(1, 512), 256, SM128>>>(Hid, 0, Wc, 512, conv_b, nullptr, X, 128, 512);

    // LocalMSA
    mma_gemm<0, 0, 128><<<dim3(3, 512), 256, SM128>>>(X, 128, qkv1_w, 128, qkv1_b, nullptr, QKV, 384, 128);
    attn1_kernel<<<NWIN, 128>>>(QKV, X);
    // MLP1
    mma_gemm<0, 1, 128><<<dim3(4, 512), 256, SM128>>>(X, 128, mlp1_w1, 128, mlp1_b1, nullptr, Hid, 512, 128);
    mma_gemm<0, 2, 128><<<dim3(1, 512), 256, SM128>>>(Hid, 512, mlp1_w2, 512, mlp1_b2, nullptr, X, 128, 512);

    // DilatedMSA: S GEMM -> stats-only softmax -> PV GEMM with inline exp
    mma_gemm<0, 0, 128><<<dim3(3, 512), 256, SM128>>>(X, 128, qkv2_w, 128, qkv2_b, nullptr, QKV, 384, 128);
    vt_kernel<<<dim3(512, 8), 256>>>(QKV, Vt);
    mma_gemm<3, 3, 128><<<dim3(2, 2, 512), 256, SM128>>>(QKV, 0, QKV, 0, nullptr, nullptr, Hid, 256, 64);
    softmax_stats<<<16384, 256>>>(Hid, stats);
    mma_gemm<5, 4, 64><<<dim3(1, 2, 512), 256, SM64>>>(Hid, 256, Vt, 256, nullptr, stats, X, 128, 256);
    // MLP2 (second GEMM fuses residual + window-reverse scatter into Xr)
    mma_gemm<0, 1, 128><<<dim3(4, 512), 256, SM128>>>(X, 128, mlp2_w1, 128, mlp2_b1, nullptr, Hid, 512, 128);
    mma_gemm<0, 6, 128><<<dim3(1, 512), 256, SM128>>>(Hid, 512, mlp2_w2, 512, mlp2_b2, X, Xr, 128, 512);

    // persistent ConvLSTM scan
    lstm_persist<<<128, 256, SM128>>>(Xr, Wl, lstm_bh, h, c, gates, out);
}

// round 13
// speedup vs baseline: 1.1877x; 1.1034x over previous
#include <cuda_runtime.h>
#include <cuda_bf16.h>
#include <cstdint>
#include <math.h>

// ===========================================================================
#define T_TOK   65536
#define NWIN    4096
#define NPIX    4096

// scratch (device globals)
__device__ float g_X  [T_TOK * 128];
__device__ float g_QKV[T_TOK * 384];
__device__ float g_Hid[(size_t)T_TOK * 512];   // NHWC x / mlp hidden / attn S
__device__ float g_Xr [T_TOK * 128];
__device__ float g_Vt [512 * 64 * 256];
__device__ float g_h  [NPIX * 128];
__device__ float g_c  [NPIX * 128];
__device__ float g_gates[NPIX * 512];
__device__ float g_Wc [128 * 512];
__device__ float g_Wl [512 * 256];
__device__ float g_stats[131072 * 2];          // per-S-row (max, 1/sum)
__device__ int   g_bar;

__device__ __forceinline__ uint32_t f2tf32(float f) {
    uint32_t u; asm("cvt.rna.tf32.f32 %0, %1;" : "=r"(u) : "f"(f)); return u;
}
__device__ __forceinline__ void mma_tf32(float* c, const uint32_t* a, const uint32_t* b) {
    asm volatile(
        "mma.sync.aligned.m16n8k8.row.col.f32.tf32.tf32.f32 "
        "{%0,%1,%2,%3}, {%4,%5,%6,%7}, {%8,%9}, {%0,%1,%2,%3};"
        : "+f"(c[0]), "+f"(c[1]), "+f"(c[2]), "+f"(c[3])
        : "r"(a[0]), "r"(a[1]), "r"(a[2]), "r"(a[3]), "r"(b[0]), "r"(b[1]));
}

// ===========================================================================
// merged prep kernel
// ===========================================================================
__global__ void prep_all(const float* __restrict__ cw, float* __restrict__ Wc,
                         const float* __restrict__ wx, const float* __restrict__ wh,
                         float* __restrict__ Wl,
                         const float* __restrict__ h0, const float* __restrict__ c0,
                         float* __restrict__ h, float* __restrict__ c) {
    int idx = blockIdx.x * 128 + threadIdx.x;
    if (idx == 0) g_bar = 0;
    if (idx < 65536) {
        int o = idx >> 9, rem = idx & 511, tap = rem >> 7, i = rem & 127;
        Wc[idx] = cw[o * 512 + i * 4 + tap];
    }
    if (idx < 131072) {
        int o = idx >> 8, k = idx & 255;
        Wl[idx] = (k < 128) ? wx[o * 128 + k] : wh[o * 128 + (k - 128)];
    }
    {
        int ch = idx >> 12, p = idx & 4095;
        h[p * 128 + ch] = h0[idx];
        c[p * 128 + ch] = c0[idx];
    }
}

// NCHW -> NHWC transpose of x (output 33.5M floats -> g_Hid)
__global__ void transpose_x(const float* __restrict__ x, float* __restrict__ xt) {
    __shared__ float t[32][33];
    int bid = blockIdx.x;
    int tile = bid & 15, by = bid >> 4;
    int i0 = (tile >> 2) * 32, x0 = (tile & 3) * 32;
    int tx = threadIdx.x & 31, ty = threadIdx.x >> 5;
    const float* xin = x + (size_t)(by >> 7) * 2097152 + (size_t)(by & 127) * 128;
#pragma unroll
    for (int k = 0; k < 4; k++)
        t[ty + k * 8][tx] = xin[(size_t)(i0 + ty + k * 8) * 16384 + x0 + tx];
    __syncthreads();
    float* xout = xt + (size_t)by * 16384;
#pragma unroll
    for (int k = 0; k < 4; k++)
        xout[(size_t)(x0 + ty + k * 8) * 128 + i0 + tx] = t[tx][ty + k * 8];
}

// ===========================================================================
// generic mma.sync tf32 GEMM, double-buffered; __launch_bounds__(256,2)
// forces regs<=128 -> 2 CTAs/SM (was 130 regs -> 1 CTA/SM, occ 11.8%).
// MODE: 0 plain | 1 conv-im2col A | 3 attn QK^T | 5 attn PV + inline softmax
// EPI: 0 bias | 1 bias+gelu | 2 bias+add-in-place | 3 scale | 4 add-in-place
//      6 bias + add-R + scatter window-reverse
// ===========================================================================
template<int MODE>
__device__ __forceinline__ const float* a_ptr(const float* A, int lda,
                                              int m, int k0, int blh) {
    if constexpr (MODE == 1) {
        int w = m >> 4, pl = m & 15;
        int b = w >> 8, yg = (w >> 4) & 15, xg = w & 15;
        int yl = pl >> 2, xl = pl & 3;
        int tap = k0 >> 7, ky = tap >> 1, kx = tap & 1;
        int Y = yg * 8 + yl * 2 + ky, XX = xg * 8 + xl * 2 + kx;
        return A + ((size_t)(b * 128 + Y) * 128 + XX) * 128 + (k0 & 127);
    } else if constexpr (MODE == 3) {
        int b = blh >> 5, l = (blh >> 1) & 15, h = blh & 1;
        return A + ((size_t)((b * 256 + m) * 16 + l)) * 384 + h * 64 + k0;
    } else if constexpr (MODE == 4 || MODE == 5) {
        return A + (size_t)blh * 65536 + (size_t)m * 256 + k0;
    } else {
        return A + (size_t)m * lda + k0;
    }
}
template<int MODE>
__device__ __forceinline__ const float* b_ptr(const float* B, int ldb, int n, int k0, int blh) {
    if constexpr (MODE == 3) {
        int b = blh >> 5, l = (blh >> 1) & 15, h = blh & 1;
        return B + ((size_t)((b * 256 + n) * 16 + l)) * 384 + 128 + h * 64 + k0;
    } else if constexpr (MODE == 4 || MODE == 5) {
        return B + (size_t)blh * 16384 + (size_t)n * 256 + k0;
    } else {
        return B + (size_t)n * ldb + k0;
    }
}

__device__ __forceinline__ float gelu_exact(float v) {
    return 0.5f * v * (1.0f + erff(v * 0.70710678118654752f));
}

template<int MODE, int EPI, int NT>
__global__ void __launch_bounds__(256, 2) mma_gemm(
        const float* __restrict__ A, int lda,
        const float* __restrict__ B, int ldb,
        const float* __restrict__ bias, const float* __restrict__ R,
        float* __restrict__ C, int ldc, int K) {
    constexpr int MW = (NT == 128) ? 2 : 4;
    constexpr int NW = 8 / MW;
    constexpr int WM = 128 / MW;
    constexpr int WN = NT / NW;
    constexpr int MI = WM / 16;
    constexpr int NI = WN / 8;
    constexpr int BUF = (128 + NT) * 36;

    extern __shared__ __align__(16) uint32_t sm[];
    __shared__ float sbias[NT];

    const int tid = threadIdx.x, wid = tid >> 5, lane = tid & 31;
    const int bm = blockIdx.y * 128, bn = blockIdx.x * NT;
    const int blh = blockIdx.z;
    const int wm0 = (wid & (MW - 1)) * WM;
    const int wn0 = (wid / MW) * WN;
    const int srow = tid >> 3, scol = tid & 7;

    if (EPI == 0 || EPI == 1 || EPI == 2 || EPI == 6) {
        for (int i = tid; i < NT; i += 256) sbias[i] = bias[bn + i];
    }

    float st_m[4], st_i[4];
    if constexpr (MODE == 5) {
#pragma unroll
        for (int it = 0; it < 4; it++) {
            int gr = blh * 256 + bm + it * 32 + srow;
            st_m[it] = R[gr * 2];
            st_i[it] = R[gr * 2 + 1];
        }
    }

    float acc[MI][NI][4];
#pragma unroll
    for (int mi = 0; mi < MI; mi++)
#pragma unroll
        for (int ni = 0; ni < NI; ni++)
#pragma unroll
            for (int q = 0; q < 4; q++) acc[mi][ni][q] = 0.f;

    float4 aReg[4];
    float4 bReg[NT / 32];

    auto ldg = [&](int k0) {
#pragma unroll
        for (int it = 0; it < 4; it++)
            aReg[it] = ((const float4*)a_ptr<MODE>(A, lda, bm + it * 32 + srow, k0, blh))[scol];
#pragma unroll
        for (int it = 0; it < NT / 32; it++)
            bReg[it] = ((const float4*)b_ptr<MODE>(B, ldb, bn + it * 32 + srow, k0, blh))[scol];
    };
    auto sts = [&](int buf) {
        uint32_t* base = sm + buf * BUF;
#pragma unroll
        for (int it = 0; it < 4; it++) {
            float4 v = aReg[it];
            if constexpr (MODE == 5) {
                v.x = expf(v.x - st_m[it]) * st_i[it];
                v.y = expf(v.y - st_m[it]) * st_i[it];
                v.z = expf(v.z - st_m[it]) * st_i[it];
                v.w = expf(v.w - st_m[it]) * st_i[it];
            }
            uint4 u = make_uint4(f2tf32(v.x), f2tf32(v.y), f2tf32(v.z), f2tf32(v.w));
            *(uint4*)&base[(it * 32 + srow) * 36 + scol * 4] = u;
        }
        uint32_t* bb = base + 128 * 36;
#pragma unroll
        for (int it = 0; it < NT / 32; it++) {
            float4 v = bReg[it];
            uint4 u = make_uint4(f2tf32(v.x), f2tf32(v.y), f2tf32(v.z), f2tf32(v.w));
            *(uint4*)&bb[(it * 32 + srow) * 36 + scol * 4] = u;
        }
    };
    auto compute = [&](int buf) {
        const uint32_t* Ab = sm + buf * BUF;
        const uint32_t* Bb = Ab + 128 * 36;
#pragma unroll
        for (int ks = 0; ks < 4; ks++) {
            int kq = ks * 8 + (lane & 3);
            uint32_t afr[MI][4];
#pragma unroll
            for (int mi = 0; mi < MI; mi++) {
                int r = wm0 + mi * 16 + (lane >> 2);
                afr[mi][0] = Ab[r * 36 + kq];
                afr[mi][1] = Ab[(r + 8) * 36 + kq];
                afr[mi][2] = Ab[r * 36 + kq + 4];
                afr[mi][3] = Ab[(r + 8) * 36 + kq + 4];
            }
            uint32_t bfr[NI][2];
#pragma unroll
            for (int ni = 0; ni < NI; ni++) {
                int n = wn0 + ni * 8 + (lane >> 2);
                bfr[ni][0] = Bb[n * 36 + kq];
                bfr[ni][1] = Bb[n * 36 + kq + 4];
            }
#pragma unroll
            for (int mi = 0; mi < MI; mi++)
#pragma unroll
                for (int ni = 0; ni < NI; ni++)
                    mma_tf32(acc[mi][ni], afr[mi], bfr[ni]);
        }
    };

    const int NCH = K >> 5;
    ldg(0);
    sts(0);
    int cur = 0;
    for (int ch = 0; ch < NCH; ch++) {
        __syncthreads();
        if (ch + 1 < NCH) ldg((ch + 1) << 5);
        compute(cur);
        if (ch + 1 < NCH) sts(cur ^ 1);
        cur ^= 1;
    }

    // ---- epilogue ----
#pragma unroll
    for (int mi = 0; mi < MI; mi++) {
#pragma unroll
        for (int ni = 0; ni < NI; ni++) {
#pragma unroll
            for (int half = 0; half < 2; half++) {
                int row = bm + wm0 + mi * 16 + (lane >> 2) + half * 8;
                int cl = wn0 + ni * 8 + 2 * (lane & 3);
                float f0 = acc[mi][ni][half * 2 + 0];
                float f1 = acc[mi][ni][half * 2 + 1];
                if constexpr (EPI == 0 || EPI == 2 || EPI == 6) { f0 += sbias[cl]; f1 += sbias[cl + 1]; }
                else if constexpr (EPI == 1) { f0 = gelu_exact(f0 + sbias[cl]); f1 = gelu_exact(f1 + sbias[cl + 1]); }
                else if constexpr (EPI == 3) { f0 *= 0.08838834764831843f; f1 *= 0.08838834764831843f; }
                float* cp;
                if constexpr (MODE == 4 || MODE == 5) {
                    int b = blh >> 5, l = (blh >> 1) & 15, h = blh & 1;
                    cp = C + ((size_t)((b * 256 + row) * 16 + l)) * 128 + h * 64 + cl;
                } else if constexpr (MODE == 3) {
                    cp = C + (size_t)blh * 65536 + (size_t)row * 256 + bn + cl;
                } else if constexpr (EPI == 6) {
                    int n_ = row >> 12, w_ = (row >> 4) & 255, pl = row & 15;
                    int p = ((w_ >> 4) * 4 + (pl >> 2)) * 64 + (w_ & 15) * 4 + (pl & 3);
                    cp = C + ((size_t)n_ * 4096 + p) * 128 + bn + cl;
                } else {
                    cp = C + (size_t)row * ldc + bn + cl;
                }
                float2 v = make_float2(f0, f1);
                if constexpr (EPI == 2 || EPI == 4) {
                    float2 o = *(float2*)cp;
                    v.x += o.x; v.y += o.y;
                }
                if constexpr (EPI == 6) {
                    float2 o = *(const float2*)(R + (size_t)row * ldc + bn + cl);
                    v.x += o.x; v.y += o.y;
                }
                *(float2*)cp = v;
            }
        }
    }
}

// ===========================================================================
// attention 1: per window (16 tokens, 2 heads, hd=64). X += attn(V)
// ===========================================================================
__global__ void attn1_kernel(const float* __restrict__ QKV, float* __restrict__ X) {
    __shared__ float q[16][384];
    __shared__ float s[2][16][16];
    int w = blockIdx.x, tid = threadIdx.x;
    size_t base = (size_t)w * 16 * 384;
    for (int i = tid; i < 16 * 384; i += 128) q[i / 384][i % 384] = QKV[base + i];
    __syncthreads();
    for (int idx = tid; idx < 512; idx += 128) {
        int h = idx >> 8, t1 = (idx >> 4) & 15, t2 = idx & 15;
        const float* qp = &q[t1][h * 64];
        const float* kp = &q[t2][128 + h * 64];
        float a = 0.f;
#pragma unroll
        for (int c = 0; c < 64; c++) a = fmaf(qp[c], kp[c], a);
        s[h][t1][t2] = a * 0.08838834764831843f;
    }
    __syncthreads();
    if (tid < 32) {
        int h = tid >> 4, t1 = tid & 15;
        float m = -1e30f;
#pragma unroll
        for (int j = 0; j < 16; j++) m = fmaxf(m, s[h][t1][j]);
        float sum = 0.f;
#pragma unroll
        for (int j = 0; j < 16; j++) { float e = expf(s[h][t1][j] - m); s[h][t1][j] = e; sum += e; }
        float inv = 1.f / sum;
#pragma unroll
        for (int j = 0; j < 16; j++) s[h][t1][j] *= inv;
    }
    __syncthreads();
    for (int idx = tid; idx < 2048; idx += 128) {
        int t1 = idx >> 7, ch = idx & 127, h = ch >> 6;
        float a = 0.f;
#pragma unroll
        for (int j = 0; j < 16; j++) a = fmaf(s[h][t1][j], q[j][256 + ch], a);
        X[(size_t)(w * 16 + t1) * 128 + ch] += a;
    }
}

// ===========================================================================
// attn2 helpers
// ===========================================================================
__global__ void vt_kernel(const float* __restrict__ QKV, float* __restrict__ Vt) {
    __shared__ float t[32][65];
    int blh = blockIdx.x, g0 = blockIdx.y * 32;
    int b = blh >> 5, l = (blh >> 1) & 15, h = blh & 1;
    int tid = threadIdx.x;
#pragma unroll
    for (int it = 0; it < 8; it++) {
        int e = tid + it * 256;
        int g = e >> 6, c = e & 63;
        t[g][c] = QKV[((size_t)((b * 256 + g0 + g) * 16 + l)) * 384 + 256 + h * 64 + c];
    }
    __syncthreads();
    float* vp = Vt + (size_t)blh * 16384;
#pragma unroll
    for (int it = 0; it < 8; it++) {
        int e = tid + it * 256;
        int c = e >> 5, g = e & 31;
        vp[(size_t)c * 256 + g0 + g] = t[g][c];
    }
}

__global__ void softmax_stats(const float* __restrict__ S, float* __restrict__ st) {
    int row = blockIdx.x * 8 + (threadIdx.x >> 5);
    int lane = threadIdx.x & 31;
    const float* r = S + (size_t)row * 256;
    float v[8];
#pragma unroll
    for (int i = 0; i < 8; i++) v[i] = r[lane + i * 32];
    float m = -1e30f;
#pragma unroll
    for (int i = 0; i < 8; i++) m = fmaxf(m, v[i]);
#pragma unroll
    for (int o = 16; o; o >>= 1) m = fmaxf(m, __shfl_xor_sync(0xffffffffu, m, o));
    float s = 0.f;
#pragma unroll
    for (int i = 0; i < 8; i++) s += expf(v[i] - m);
#pragma unroll
    for (int o = 16; o; o >>= 1) s += __shfl_xor_sync(0xffffffffu, s, o);
    if (lane == 0) {
        st[row * 2]     = m;
        st[row * 2 + 1] = 1.f / s;
    }
}

// ===========================================================================
// persistent ConvLSTM (unchanged champion)
// ===========================================================================
__device__ __forceinline__ void grid_barrier(int target) {
    __syncthreads();
    if (threadIdx.x == 0) {
        __threadfence();
        atomicAdd(&g_bar, 1);
        while (atomicAdd(&g_bar, 0) < target) { }
    }
    __syncthreads();
}

__global__ void __launch_bounds__(256) lstm_persist(
        const float* __restrict__ Xr, const float* __restrict__ Wl,
        const float* __restrict__ bias,
        float* __restrict__ h, float* __restrict__ c,
        float* __restrict__ gates, float* __restrict__ out) {
    extern __shared__ __align__(16) uint32_t stg[];
    __shared__ float ht[32 * 129];
    __shared__ float sbias[128];

    const int tid = threadIdx.x, wid = tid >> 5, lane = tid & 31;
    const int blk = blockIdx.x;
    const int bn = blk & 3, bm = blk >> 2;
    const int P0 = bm * 128;
    const int q0 = blk * 32;
    const int wm0 = (wid & 1) * 64;
    const int wn0 = (wid >> 1) * 32;
    const int srow = tid >> 3, scol = tid & 7;
    constexpr int BUF = 256 * 36;

    if (tid < 128) sbias[tid] = bias[bn * 128 + tid];
    int barcnt = 0;

    for (int n = 0; n < 16; n++) {
        const float* Xn = Xr + (size_t)n * NPIX * 128;
        float acc[4][4][4];
#pragma unroll
        for (int mi = 0; mi < 4; mi++)
#pragma unroll
            for (int ni = 0; ni < 4; ni++)
#pragma unroll
                for (int q = 0; q < 4; q++) acc[mi][ni][q] = 0.f;

        float4 aReg[4], bReg[4];
        auto ldg = [&](int k0) {
#pragma unroll
            for (int it = 0; it < 4; it++) {
                int row = P0 + it * 32 + srow;
                if (k0 < 128)
                    aReg[it] = *(const float4*)&Xn[(size_t)row * 128 + k0 + scol * 4];
                else
                    aReg[it] = __ldcg((const float4*)&h[(size_t)row * 128 + (k0 - 128) + scol * 4]);
            }
#pragma unroll
            for (int it = 0; it < 4; it++)
                bReg[it] = *(const float4*)&Wl[(size_t)(bn * 128 + it * 32 + srow) * 256 + k0 + scol * 4];
        };
        auto sts = [&](int buf) {
            uint32_t* base = stg + buf * BUF;
#pragma unroll
            for (int it = 0; it < 4; it++) {
                float4 v = aReg[it];
                uint4 u = make_uint4(f2tf32(v.x), f2tf32(v.y), f2tf32(v.z), f2tf32(v.w));
                *(uint4*)&base[(it * 32 + srow) * 36 + scol * 4] = u;
            }
            uint32_t* bb = base + 128 * 36;
#pragma unroll
            for (int it = 0; it < 4; it++) {
                float4 v = bReg[it];
                uint4 u = make_uint4(f2tf32(v.x), f2tf32(v.y), f2tf32(v.z), f2tf32(v.w));
                *(uint4*)&bb[(it * 32 + srow) * 36 + scol * 4] = u;
            }
        };
        auto compute = [&](int buf) {
            const uint32_t* Ab = stg + buf * BUF;
            const uint32_t* Bb = Ab + 128 * 36;
#pragma unroll
            for (int ks = 0; ks < 4; ks++) {
                int kq = ks * 8 + (lane & 3);
                uint32_t afr[4][4];
#pragma unroll
                for (int mi = 0; mi < 4; mi++) {
                    int r = wm0 + mi * 16 + (lane >> 2);
                    afr[mi][0] = Ab[r * 36 + kq];
                    afr[mi][1] = Ab[(r + 8) * 36 + kq];
                    afr[mi][2] = Ab[r * 36 + kq + 4];
                    afr[mi][3] = Ab[(r + 8) * 36 + kq + 4];
                }
                uint32_t bfr[4][2];
#pragma unroll
                for (int ni = 0; ni < 4; ni++) {
                    int nn = wn0 + ni * 8 + (lane >> 2);
                    bfr[ni][0] = Bb[nn * 36 + kq];
                    bfr[ni][1] = Bb[nn * 36 + kq + 4];
                }
#pragma unroll
                for (int mi = 0; mi < 4; mi++)
#pragma unroll
                    for (int ni = 0; ni < 4; ni++)
                        mma_tf32(acc[mi][ni], afr[mi], bfr[ni]);
            }
        };

        ldg(0);
        sts(0);
        int cur = 0;
        for (int ch = 0; ch < 8; ch++) {
            __syncthreads();
            if (ch + 1 < 8) ldg((ch + 1) << 5);
            compute(cur);
            if (ch + 1 < 8) sts(cur ^ 1);
            cur ^= 1;
        }
#pragma unroll
        for (int mi = 0; mi < 4; mi++) {
#pragma unroll
            for (int ni = 0; ni < 4; ni++) {
#pragma unroll
                for (int half = 0; half < 2; half++) {
                    int row = wm0 + mi * 16 + (lane >> 2) + half * 8;
                    int cl = wn0 + ni * 8 + 2 * (lane & 3);
                    float2 v = make_float2(acc[mi][ni][half * 2 + 0] + sbias[cl],
                                           acc[mi][ni][half * 2 + 1] + sbias[cl + 1]);
                    *(float2*)&gates[(size_t)(P0 + row) * 512 + bn * 128 + cl] = v;
                }
            }
        }
        grid_barrier(128 * (++barcnt));

#pragma unroll 1
        for (int it = 0; it < 4; it++) {
            int pl = wid * 4 + it;
            int p = q0 + pl;
            const float* gp = gates + (size_t)p * 512;
            float fv[4], iv[4], sv[4], ov[4];
#pragma unroll
            for (int j = 0; j < 4; j++) {
                int ch = lane + j * 32;
                fv[j] = __ldcg(gp + ch);        iv[j] = __ldcg(gp + 128 + ch);
                sv[j] = __ldcg(gp + 256 + ch);  ov[j] = __ldcg(gp + 384 + ch);
            }
            float mf = fmaxf(fmaxf(fv[0], fv[1]), fmaxf(fv[2], fv[3]));
            float mi = fmaxf(fmaxf(iv[0], iv[1]), fmaxf(iv[2], iv[3]));
            float mo = fmaxf(fmaxf(ov[0], ov[1]), fmaxf(ov[2], ov[3]));
#pragma unroll
            for (int o = 16; o; o >>= 1) {
                mf = fmaxf(mf, __shfl_xor_sync(0xffffffffu, mf, o));
                mi = fmaxf(mi, __shfl_xor_sync(0xffffffffu, mi, o));
                mo = fmaxf(mo, __shfl_xor_sync(0xffffffffu, mo, o));
            }
            float sf = 0.f, si = 0.f, so = 0.f;
#pragma unroll
            for (int j = 0; j < 4; j++) {
                fv[j] = expf(fv[j] - mf); sf += fv[j];
                iv[j] = expf(iv[j] - mi); si += iv[j];
                ov[j] = expf(ov[j] - mo); so += ov[j];
            }
#pragma unroll
            for (int o = 16; o; o >>= 1) {
                sf += __shfl_xor_sync(0xffffffffu, sf, o);
                si += __shfl_xor_sync(0xffffffffu, si, o);
                so += __shfl_xor_sync(0xffffffffu, so, o);
            }
            float rf = 1.f / sf, ri = 1.f / si, ro = 1.f / so;
#pragma unroll
            for (int j = 0; j < 4; j++) {
                int ch = lane + j * 32;
                float cc = c[(size_t)p * 128 + ch];
                float cn = fv[j] * rf * cc + iv[j] * ri * tanhf(sv[j]);
                float hn = ov[j] * ro * tanhf(cn);
                c[(size_t)p * 128 + ch] = cn;
                h[(size_t)p * 128 + ch] = hn;
                ht[pl * 129 + ch] = hn;
            }
        }
        __syncthreads();
        for (int i = tid; i < 4096; i += 256) {
            int ch = i >> 5, pl = i & 31;
            float hv = ht[pl * 129 + ch];
            out[((size_t)(n * 128 + ch)) * 4096 + q0 + pl] = hv;
            if (n == 15) out[((size_t)(16 * 128 + ch)) * 4096 + q0 + pl] = hv;
        }
        if (n == 15) {
            __syncthreads();
            for (int i = tid; i < 4096; i += 256) {
                int ch = i >> 5, pl = i & 31;
                ht[pl * 129 + ch] = c[(size_t)(q0 + pl) * 128 + ch];
            }
            __syncthreads();
            for (int i = tid; i < 4096; i += 256) {
                int ch = i >> 5, pl = i & 31;
                out[((size_t)(17 * 128 + ch)) * 4096 + q0 + pl] = ht[pl * 129 + ch];
            }
        }
        grid_barrier(128 * (++barcnt));
    }
}

// ===========================================================================
extern "C" void kernel_launch(void* const* d_in, const int* in_sizes, int n_in,
                              void* d_out, int out_size) {
    const float* x       = (const float*)d_in[0];
    const float* h0      = (const float*)d_in[1];
    const float* c0      = (const float*)d_in[2];
    const float* conv_w  = (const float*)d_in[3];
    const float* conv_b  = (const float*)d_in[4];
    const float* qkv1_w  = (const float*)d_in[5];
    const float* qkv1_b  = (const float*)d_in[6];
    const float* mlp1_w1 = (const float*)d_in[7];
    const float* mlp1_b1 = (const float*)d_in[8];
    const float* mlp1_w2 = (const float*)d_in[9];
    const float* mlp1_b2 = (const float*)d_in[10];
    const float* qkv2_w  = (const float*)d_in[11];
    const float* qkv2_b  = (const float*)d_in[12];
    const float* mlp2_w1 = (const float*)d_in[13];
    const float* mlp2_b1 = (const float*)d_in[14];
    const float* mlp2_w2 = (const float*)d_in[15];
    const float* mlp2_b2 = (const float*)d_in[16];
    const float* lstm_wx = (const float*)d_in[17];
    const float* lstm_wh = (const float*)d_in[18];
    const float* lstm_bh = (const float*)d_in[19];
    float* out = (float*)d_out;
    (void)in_sizes; (void)n_in; (void)out_size;

    float *X, *QKV, *Hid, *Xr, *Vt, *h, *c, *gates, *Wc, *Wl, *stats;
    cudaGetSymbolAddress((void**)&X, g_X);
    cudaGetSymbolAddress((void**)&QKV, g_QKV);
    cudaGetSymbolAddress((void**)&Hid, g_Hid);
    cudaGetSymbolAddress((void**)&Xr, g_Xr);
    cudaGetSymbolAddress((void**)&Vt, g_Vt);
    cudaGetSymbolAddress((void**)&h, g_h);
    cudaGetSymbolAddress((void**)&c, g_c);
    cudaGetSymbolAddress((void**)&gates, g_gates);
    cudaGetSymbolAddress((void**)&Wc, g_Wc);
    cudaGetSymbolAddress((void**)&Wl, g_Wl);
    cudaGetSymbolAddress((void**)&stats, g_stats);

    const int SM128 = 2 * (128 + 128) * 36 * 4;                 // 73728
    const int SM64  = 2 * (128 + 64) * 36 * 4;                  // 55296
    cudaFuncSetAttribute((const void*)mma_gemm<1, 0, 128>, cudaFuncAttributeMaxDynamicSharedMemorySize, SM128);
    cudaFuncSetAttribute((const void*)mma_gemm<0, 0, 128>, cudaFuncAttributeMaxDynamicSharedMemorySize, SM128);
    cudaFuncSetAttribute((const void*)mma_gemm<0, 1, 128>, cudaFuncAttributeMaxDynamicSharedMemorySize, SM128);
    cudaFuncSetAttribute((const void*)mma_gemm<0, 2, 128>, cudaFuncAttributeMaxDynamicSharedMemorySize, SM128);
    cudaFuncSetAttribute((const void*)mma_gemm<0, 6, 128>, cudaFuncAttributeMaxDynamicSharedMemorySize, SM128);
    cudaFuncSetAttribute((const void*)mma_gemm<3, 3, 128>, cudaFuncAttributeMaxDynamicSharedMemorySize, SM128);
    cudaFuncSetAttribute((const void*)mma_gemm<5, 4, 64>,  cudaFuncAttributeMaxDynamicSharedMemorySize, SM64);
    cudaFuncSetAttribute((const void*)lstm_persist, cudaFuncAttributeMaxDynamicSharedMemorySize, SM128);

    prep_all<<<4096, 128>>>(conv_w, Wc, lstm_wx, lstm_wh, Wl, h0, c0, h, c);
    transpose_x<<<32768, 256>>>(x, Hid);

    // conv as implicit-im2col GEMM
    mma_gemm<1, 0, 128><<<dim3(1, 512), 256, SM128>>>(Hid, 0, Wc, 512, conv_b, nullptr, X, 128, 512);

    // LocalMSA
    mma_gemm<0, 0, 128><<<dim3(3, 512), 256, SM128>>>(X, 128, qkv1_w, 128, qkv1_b, nullptr, QKV, 384, 128);
    attn1_kernel<<<NWIN, 128>>>(QKV, X);
    // MLP1
    mma_gemm<0, 1, 128><<<dim3(4, 512), 256, SM128>>>(X, 128, mlp1_w1, 128, mlp1_b1, nullptr, Hid, 512, 128);
    mma_gemm<0, 2, 128><<<dim3(1, 512), 256, SM128>>>(Hid, 512, mlp1_w2, 512, mlp1_b2, nullptr, X, 128, 512);

    // DilatedMSA
    mma_gemm<0, 0, 128><<<dim3(3, 512), 256, SM128>>>(X, 128, qkv2_w, 128, qkv2_b, nullptr, QKV, 384, 128);
    vt_kernel<<<dim3(512, 8), 256>>>(QKV, Vt);
    mma_gemm<3, 3, 128><<<dim3(2, 2, 512), 256, SM128>>>(QKV, 0, QKV, 0, nullptr, nullptr, Hid, 256, 64);
    softmax_stats<<<16384, 256>>>(Hid, stats);
    mma_gemm<5, 4, 64><<<dim3(1, 2, 512), 256, SM64>>>(Hid, 256, Vt, 256, nullptr, stats, X, 128, 256);
    // MLP2
    mma_gemm<0, 1, 128><<<dim3(4, 512), 256, SM128>>>(X, 128, mlp2_w1, 128, mlp2_b1, nullptr, Hid, 512, 128);
    mma_gemm<0, 6, 128><<<dim3(1, 512), 256, SM128>>>(Hid, 512, mlp2_w2, 512, mlp2_b2, X, Xr, 128, 512);

    // persistent ConvLSTM scan
    lstm_persist<<<128, 256, SM128>>>(Xr, Wl, lstm_bh, h, c, gates, out);
}